// round 5
// baseline (speedup 1.0000x reference)
#include <cuda_runtime.h>
#include <cstdint>

#define NR0 4096
#define NR1 8192
#define NR2 4096
#define NT  16384     // NR0+NR1+NR2
#define C   64
#define OUTC 32
#define NB  64

// ---- scratch (device globals; no allocation allowed) ----
__device__ float    g_dinv[NT];
__device__ uint16_t g_zhi[C * NT];    // bf16 hi of z^T [C][NT] (K-major B operand)
__device__ uint16_t g_zlo[C * NT];    // bf16 lo
__device__ float    g_xA[NT * C];
__device__ float    g_xB[NT * C];
__device__ float    g_pooled[3 * NB * C];

// ============================================================
// helpers
// ============================================================
__device__ __forceinline__ uint32_t pack_bf16(float lo, float hi) {
    uint32_t r;
    asm("cvt.rn.bf16x2.f32 %0, %1, %2;" : "=r"(r) : "f"(hi), "f"(lo));
    return r;
}
__device__ __forceinline__ uint16_t bf16_rn(float x) {
    uint16_t r;
    asm("cvt.rn.bf16.f32 %0, %1;" : "=h"(r) : "f"(x));
    return r;
}
__device__ __forceinline__ void mma_bf16(float* c, const uint32_t* a, const uint32_t* b) {
    asm volatile("mma.sync.aligned.m16n8k16.row.col.f32.bf16.bf16.f32 "
        "{%0,%1,%2,%3}, {%4,%5,%6,%7}, {%8,%9}, {%0,%1,%2,%3};"
        : "+f"(c[0]), "+f"(c[1]), "+f"(c[2]), "+f"(c[3])
        : "r"(a[0]), "r"(a[1]), "r"(a[2]), "r"(a[3]), "r"(b[0]), "r"(b[1]));
}

// ============================================================
// dinv[i] = rsqrt(rowsum |L_i|), 0 if rowsum == 0
// ============================================================
__global__ void dinv_kernel(const float* __restrict__ L0,
                            const float* __restrict__ L1,
                            const float* __restrict__ L2) {
    int grow = blockIdx.x;
    const float* L; int N; int lr;
    if (grow < NR0)             { L = L0; N = NR0; lr = grow; }
    else if (grow < NR0 + NR1)  { L = L1; N = NR1; lr = grow - NR0; }
    else                        { L = L2; N = NR2; lr = grow - NR0 - NR1; }

    const float4* row = (const float4*)(L + (size_t)lr * N);
    int n4 = N >> 2;
    float s = 0.f;
    for (int j = threadIdx.x; j < n4; j += blockDim.x) {
        float4 v = row[j];
        s += fabsf(v.x) + fabsf(v.y) + fabsf(v.z) + fabsf(v.w);
    }
    __shared__ float red[4];
    for (int o = 16; o > 0; o >>= 1) s += __shfl_down_sync(0xffffffffu, s, o);
    if ((threadIdx.x & 31) == 0) red[threadIdx.x >> 5] = s;
    __syncthreads();
    if (threadIdx.x == 0) {
        float d = red[0] + red[1] + red[2] + red[3];
        g_dinv[grow] = (d != 0.f) ? rsqrtf(d) : 0.f;
    }
}

// ============================================================
// z = dinv .* (x @ W[layer]); emit bf16 hi/lo transposed [C][NT]
// ============================================================
__global__ __launch_bounds__(256) void xw_kernel(
    const float* __restrict__ x0, const float* __restrict__ x1,
    const float* __restrict__ x2,
    const float* __restrict__ W0, const float* __restrict__ W1,
    const float* __restrict__ W2, int layer)
{
    __shared__ float Ws[C * C];
    __shared__ float xs[32 * C];
    __shared__ float zs[32][C + 1];

    int growBase = blockIdx.x * 32;
    const float* W; const float* xsrc;
    if (growBase < NR0) {
        W = W0;
        xsrc = layer ? (g_xA + (size_t)growBase * C) : (x0 + (size_t)growBase * C);
    } else if (growBase < NR0 + NR1) {
        W = W1;
        xsrc = layer ? (g_xA + (size_t)growBase * C) : (x1 + (size_t)(growBase - NR0) * C);
    } else {
        W = W2;
        xsrc = layer ? (g_xA + (size_t)growBase * C) : (x2 + (size_t)(growBase - NR0 - NR1) * C);
    }
    W += layer * C * C;

    int tid = threadIdx.x;
    for (int i = tid; i < C * C; i += 256) Ws[i] = W[i];
    for (int i = tid; i < 32 * C; i += 256) xs[i] = xsrc[i];
    __syncthreads();

    int c = tid & 63, rb = tid >> 6;
    #pragma unroll
    for (int rq = 0; rq < 8; rq++) {
        int r = rb * 8 + rq;
        float acc = 0.f;
        #pragma unroll
        for (int k = 0; k < C; k++) acc += xs[r * C + k] * Ws[k * C + c];
        zs[r][c] = acc * g_dinv[growBase + r];
    }
    __syncthreads();

    int c2 = tid >> 2, seg = tid & 3;
    size_t base = (size_t)c2 * NT + growBase + seg * 8;
    uint16_t hv[8], lv[8];
    #pragma unroll
    for (int j = 0; j < 8; j++) {
        float v = zs[seg * 8 + j][c2];
        uint16_t h = bf16_rn(v);
        hv[j] = h;
        lv[j] = bf16_rn(v - __uint_as_float((uint32_t)h << 16));
    }
    *(uint4*)&g_zhi[base] = *(uint4*)hv;
    *(uint4*)&g_zlo[base] = *(uint4*)lv;
}

// ============================================================
// mma.sync bf16x3 GEMM:  dst = relu(dinv .* (L @ z))
// BM=64, BN=64, BK=32, double-buffered, 128 thr = 4 warps (2m x 2n),
// warp tile m32n32. 256 CTAs, rank1 (long) first; 2 CTAs/SM.
// ============================================================
#define SA 40   // smem row pitch in halves
#define SB 40
#define AH_OFF 0
#define AL_OFF (64 * SA)
#define BH_OFF (2 * 64 * SA)
#define BL_OFF (2 * 64 * SA + C * SB)
#define STAGE_HALVES (2 * 64 * SA + 2 * C * SB)
#define GEMM_SMEM (2 * STAGE_HALVES * 2)   // bytes = 40960

__global__ __launch_bounds__(128, 2) void gemm_mma(
    const float* __restrict__ L0, const float* __restrict__ L1,
    const float* __restrict__ L2, int layer)
{
    extern __shared__ __align__(16) uint16_t sm[];

    // rank-1 CTAs first (longest jobs start in wave 1)
    int bx = blockIdx.x;
    const float* L; int N, lrowBase, growBase;
    if (bx < 128)      { L = L1; N = NR1; lrowBase = bx * 64;         growBase = NR0 + lrowBase; }
    else if (bx < 192) { L = L0; N = NR0; lrowBase = (bx - 128) * 64; growBase = lrowBase; }
    else               { L = L2; N = NR2; lrowBase = (bx - 192) * 64; growBase = NR0 + NR1 + lrowBase; }
    int zOff = growBase - lrowBase;
    int nc = N / 32;
    float* dst = layer ? g_xB : g_xA;

    int tid = threadIdx.x;
    int wid = tid >> 5, lane = tid & 31;
    int g = lane >> 2, tg = lane & 3;
    int wm = wid >> 1, wn = wid & 1;

    // ---- loader setup ----
    // A: 64 rows x 32 k -> 512 float4, 4 per thread
    const float* aPtr[4]; int aSts[4];
    #pragma unroll
    for (int q = 0; q < 4; q++) {
        int idx = q * 128 + tid;
        int aRow = idx >> 3, aK4 = idx & 7;
        aPtr[q] = L + (size_t)(lrowBase + aRow) * N + aK4 * 4;
        aSts[q] = aRow * SA + aK4 * 4;
    }
    // B: 64 rows x 4 k8-groups -> 256 uint4 each for hi/lo, 2 per thread
    const uint16_t* bhPtr[2]; const uint16_t* blPtr[2]; int bSts[2];
    #pragma unroll
    for (int q = 0; q < 2; q++) {
        int idx = q * 128 + tid;
        int bRow = idx >> 2, bK8 = idx & 3;
        bhPtr[q] = g_zhi + (size_t)bRow * NT + zOff + bK8 * 8;
        blPtr[q] = g_zlo + (size_t)bRow * NT + zOff + bK8 * 8;
        bSts[q] = bRow * SB + bK8 * 8;
    }

    float acc[2][4][4];
    #pragma unroll
    for (int mt = 0; mt < 2; mt++)
        #pragma unroll
        for (int nt = 0; nt < 4; nt++)
            #pragma unroll
            for (int i = 0; i < 4; i++) acc[mt][nt][i] = 0.f;

    float4 ra[4]; uint4 rbh[2], rbl[2];

    // ---- prologue: chunk 0 -> smem stage 0; chunk 1 -> regs ----
    #pragma unroll
    for (int q = 0; q < 4; q++) ra[q] = *(const float4*)(aPtr[q]);
    #pragma unroll
    for (int q = 0; q < 2; q++) {
        rbh[q] = *(const uint4*)bhPtr[q];
        rbl[q] = *(const uint4*)blPtr[q];
    }
    {
        uint16_t* st = sm;
        #pragma unroll
        for (int q = 0; q < 4; q++) {
            float4 v = ra[q];
            uint32_t h0 = pack_bf16(v.x, v.y);
            uint32_t h1 = pack_bf16(v.z, v.w);
            float r0 = v.x - __uint_as_float(h0 << 16);
            float r1 = v.y - __uint_as_float(h0 & 0xFFFF0000u);
            float r2 = v.z - __uint_as_float(h1 << 16);
            float r3 = v.w - __uint_as_float(h1 & 0xFFFF0000u);
            *(uint2*)&st[AH_OFF + aSts[q]] = make_uint2(h0, h1);
            *(uint2*)&st[AL_OFF + aSts[q]] = make_uint2(pack_bf16(r0, r1), pack_bf16(r2, r3));
        }
        #pragma unroll
        for (int q = 0; q < 2; q++) {
            *(uint4*)&st[BH_OFF + bSts[q]] = rbh[q];
            *(uint4*)&st[BL_OFF + bSts[q]] = rbl[q];
        }
    }
    if (nc > 1) {
        #pragma unroll
        for (int q = 0; q < 4; q++) ra[q] = *(const float4*)(aPtr[q] + 32);
        #pragma unroll
        for (int q = 0; q < 2; q++) {
            rbh[q] = *(const uint4*)(bhPtr[q] + 32);
            rbl[q] = *(const uint4*)(blPtr[q] + 32);
        }
    }
    __syncthreads();

    // ---- mainloop: one barrier per chunk ----
    for (int cI = 0; cI < nc; cI++) {
        if (cI + 1 < nc) {
            uint16_t* st = sm + ((cI + 1) & 1) * STAGE_HALVES;
            #pragma unroll
            for (int q = 0; q < 4; q++) {
                float4 v = ra[q];
                uint32_t h0 = pack_bf16(v.x, v.y);
                uint32_t h1 = pack_bf16(v.z, v.w);
                float r0 = v.x - __uint_as_float(h0 << 16);
                float r1 = v.y - __uint_as_float(h0 & 0xFFFF0000u);
                float r2 = v.z - __uint_as_float(h1 << 16);
                float r3 = v.w - __uint_as_float(h1 & 0xFFFF0000u);
                *(uint2*)&st[AH_OFF + aSts[q]] = make_uint2(h0, h1);
                *(uint2*)&st[AL_OFF + aSts[q]] = make_uint2(pack_bf16(r0, r1), pack_bf16(r2, r3));
            }
            #pragma unroll
            for (int q = 0; q < 2; q++) {
                *(uint4*)&st[BH_OFF + bSts[q]] = rbh[q];
                *(uint4*)&st[BL_OFF + bSts[q]] = rbl[q];
            }
        }
        if (cI + 2 < nc) {
            int k0 = (cI + 2) * 32;
            #pragma unroll
            for (int q = 0; q < 4; q++) ra[q] = *(const float4*)(aPtr[q] + k0);
            #pragma unroll
            for (int q = 0; q < 2; q++) {
                rbh[q] = *(const uint4*)(bhPtr[q] + k0);
                rbl[q] = *(const uint4*)(blPtr[q] + k0);
            }
        }

        const uint16_t* st = sm + (cI & 1) * STAGE_HALVES;
        #pragma unroll
        for (int ks = 0; ks < 2; ks++) {
            uint32_t ah[2][4], al[2][4];
            #pragma unroll
            for (int mt = 0; mt < 2; mt++) {
                int r0 = (wm * 32 + mt * 16 + g) * SA + ks * 16 + tg * 2;
                ah[mt][0] = *(const uint32_t*)&st[AH_OFF + r0];
                ah[mt][1] = *(const uint32_t*)&st[AH_OFF + r0 + 8 * SA];
                ah[mt][2] = *(const uint32_t*)&st[AH_OFF + r0 + 8];
                ah[mt][3] = *(const uint32_t*)&st[AH_OFF + r0 + 8 * SA + 8];
                al[mt][0] = *(const uint32_t*)&st[AL_OFF + r0];
                al[mt][1] = *(const uint32_t*)&st[AL_OFF + r0 + 8 * SA];
                al[mt][2] = *(const uint32_t*)&st[AL_OFF + r0 + 8];
                al[mt][3] = *(const uint32_t*)&st[AL_OFF + r0 + 8 * SA + 8];
            }
            uint32_t bh[4][2], bl[4][2];
            #pragma unroll
            for (int nt = 0; nt < 4; nt++) {
                int b0 = (wn * 32 + nt * 8 + g) * SB + ks * 16 + tg * 2;
                bh[nt][0] = *(const uint32_t*)&st[BH_OFF + b0];
                bh[nt][1] = *(const uint32_t*)&st[BH_OFF + b0 + 8];
                bl[nt][0] = *(const uint32_t*)&st[BL_OFF + b0];
                bl[nt][1] = *(const uint32_t*)&st[BL_OFF + b0 + 8];
            }
            #pragma unroll
            for (int mt = 0; mt < 2; mt++)
                #pragma unroll
                for (int nt = 0; nt < 4; nt++) {
                    mma_bf16(acc[mt][nt], ah[mt], bh[nt]);
                    mma_bf16(acc[mt][nt], ah[mt], bl[nt]);
                    mma_bf16(acc[mt][nt], al[mt], bh[nt]);
                }
        }
        __syncthreads();
    }

    // ---- epilogue: dinv row-scale + relu, write fp32 ----
    #pragma unroll
    for (int mt = 0; mt < 2; mt++) {
        int row0 = wm * 32 + mt * 16 + g;
        float dv0 = g_dinv[growBase + row0];
        float dv1 = g_dinv[growBase + row0 + 8];
        #pragma unroll
        for (int nt = 0; nt < 4; nt++) {
            int col = wn * 32 + nt * 8 + tg * 2;
            float* c = acc[mt][nt];
            float2 o0, o1;
            o0.x = fmaxf(c[0] * dv0, 0.f);
            o0.y = fmaxf(c[1] * dv0, 0.f);
            o1.x = fmaxf(c[2] * dv1, 0.f);
            o1.y = fmaxf(c[3] * dv1, 0.f);
            *(float2*)&dst[(size_t)(growBase + row0) * C + col]     = o0;
            *(float2*)&dst[(size_t)(growBase + row0 + 8) * C + col] = o1;
        }
    }
}

// ============================================================
// readout
// ============================================================
__global__ void zero_pooled_kernel() {
    int i = blockIdx.x * blockDim.x + threadIdx.x;
    if (i < 3 * NB * C) g_pooled[i] = 0.f;
}

__global__ void pool_kernel(const int* __restrict__ bel0,
                            const int* __restrict__ bel1,
                            const int* __restrict__ bel2) {
    int grow = blockIdx.x;
    int rank, lr;
    if (grow < NR0)            { rank = 0; lr = grow; }
    else if (grow < NR0 + NR1) { rank = 1; lr = grow - NR0; }
    else                       { rank = 2; lr = grow - NR0 - NR1; }
    const int* bel = (rank == 0) ? bel0 : (rank == 1 ? bel1 : bel2);
    int b = bel[lr];
    float v = g_xB[(size_t)grow * C + threadIdx.x];
    atomicAdd(&g_pooled[rank * NB * C + b * C + threadIdx.x], v);
}

__global__ void out_kernel(const float* __restrict__ Wr0, const float* __restrict__ br0,
                           const float* __restrict__ Wr1, const float* __restrict__ br1,
                           const float* __restrict__ Wr2, const float* __restrict__ br2,
                           float* __restrict__ out) {
    int b = blockIdx.x;
    int o = threadIdx.x;
    float acc = br0[o] + br1[o] + br2[o];
    const float* Wrs[3] = {Wr0, Wr1, Wr2};
    #pragma unroll
    for (int r = 0; r < 3; r++) {
        const float* Wr = Wrs[r];
        const float* p  = &g_pooled[r * NB * C + b * C];
        #pragma unroll 8
        for (int c = 0; c < C; c++) acc += p[c] * Wr[c * OUTC + o];
    }
    out[b * OUTC + o] = acc;
}

// ============================================================
extern "C" void kernel_launch(void* const* d_in, const int* in_sizes, int n_in,
                              void* d_out, int out_size) {
    const float* x0  = (const float*)d_in[0];
    const float* x1  = (const float*)d_in[1];
    const float* x2  = (const float*)d_in[2];
    const float* L0  = (const float*)d_in[3];
    const float* L1  = (const float*)d_in[4];
    const float* L2  = (const float*)d_in[5];
    const int*   bel0 = (const int*)d_in[6];
    const int*   bel1 = (const int*)d_in[7];
    const int*   bel2 = (const int*)d_in[8];
    const float* W0  = (const float*)d_in[9];
    const float* W1  = (const float*)d_in[10];
    const float* W2  = (const float*)d_in[11];
    const float* Wr0 = (const float*)d_in[12];
    const float* br0 = (const float*)d_in[13];
    const float* Wr1 = (const float*)d_in[14];
    const float* br1 = (const float*)d_in[15];
    const float* Wr2 = (const float*)d_in[16];
    const float* br2 = (const float*)d_in[17];

    cudaFuncSetAttribute(gemm_mma, cudaFuncAttributeMaxDynamicSharedMemorySize, GEMM_SMEM);

    dinv_kernel<<<NT, 128>>>(L0, L1, L2);

    for (int layer = 0; layer < 2; layer++) {
        xw_kernel<<<NT / 32, 256>>>(x0, x1, x2, W0, W1, W2, layer);
        gemm_mma<<<256, 128, GEMM_SMEM>>>(L0, L1, L2, layer);
    }

    zero_pooled_kernel<<<(3 * NB * C + 255) / 256, 256>>>();
    pool_kernel<<<NT, 64>>>(bel0, bel1, bel2);
    out_kernel<<<NB, OUTC>>>(Wr0, br0, Wr1, br1, Wr2, br2, (float*)d_out);
}

// round 6
// speedup vs baseline: 1.0540x; 1.0540x over previous
#include <cuda_runtime.h>
#include <cstdint>

#define NR0 4096
#define NR1 8192
#define NR2 4096
#define NT  16384     // NR0+NR1+NR2
#define C   64
#define OUTC 32
#define NB  64

// ---- scratch (device globals; no allocation allowed) ----
__device__ float    g_dinv[NT];
__device__ uint16_t g_zhi[C * NT];    // bf16 hi of z^T [C][NT] (K-major B operand)
__device__ uint16_t g_zlo[C * NT];    // bf16 lo
__device__ float    g_xA[NT * C];
__device__ float    g_xB[NT * C];
__device__ float    g_pooled[3 * NB * C];

// ============================================================
// helpers
// ============================================================
__device__ __forceinline__ uint32_t pack_bf16(float lo, float hi) {
    uint32_t r;
    asm("cvt.rn.bf16x2.f32 %0, %1, %2;" : "=r"(r) : "f"(hi), "f"(lo));
    return r;
}
__device__ __forceinline__ uint16_t bf16_rn(float x) {
    uint16_t r;
    asm("cvt.rn.bf16.f32 %0, %1;" : "=h"(r) : "f"(x));
    return r;
}
__device__ __forceinline__ void mma_bf16(float* c, const uint32_t* a, const uint32_t* b) {
    asm volatile("mma.sync.aligned.m16n8k16.row.col.f32.bf16.bf16.f32 "
        "{%0,%1,%2,%3}, {%4,%5,%6,%7}, {%8,%9}, {%0,%1,%2,%3};"
        : "+f"(c[0]), "+f"(c[1]), "+f"(c[2]), "+f"(c[3])
        : "r"(a[0]), "r"(a[1]), "r"(a[2]), "r"(a[3]), "r"(b[0]), "r"(b[1]));
}

// ============================================================
// dinv[i] = rsqrt(rowsum |L_i|), 0 if rowsum == 0
// ============================================================
__global__ void dinv_kernel(const float* __restrict__ L0,
                            const float* __restrict__ L1,
                            const float* __restrict__ L2) {
    int grow = blockIdx.x;
    const float* L; int N; int lr;
    if (grow < NR0)             { L = L0; N = NR0; lr = grow; }
    else if (grow < NR0 + NR1)  { L = L1; N = NR1; lr = grow - NR0; }
    else                        { L = L2; N = NR2; lr = grow - NR0 - NR1; }

    const float4* row = (const float4*)(L + (size_t)lr * N);
    int n4 = N >> 2;
    float s = 0.f;
    for (int j = threadIdx.x; j < n4; j += blockDim.x) {
        float4 v = row[j];
        s += fabsf(v.x) + fabsf(v.y) + fabsf(v.z) + fabsf(v.w);
    }
    __shared__ float red[4];
    for (int o = 16; o > 0; o >>= 1) s += __shfl_down_sync(0xffffffffu, s, o);
    if ((threadIdx.x & 31) == 0) red[threadIdx.x >> 5] = s;
    __syncthreads();
    if (threadIdx.x == 0) {
        float d = red[0] + red[1] + red[2] + red[3];
        g_dinv[grow] = (d != 0.f) ? rsqrtf(d) : 0.f;
    }
}

// ============================================================
// z = dinv .* (x @ W[layer]); emit bf16 hi/lo transposed [C][NT]
// ============================================================
__global__ __launch_bounds__(256) void xw_kernel(
    const float* __restrict__ x0, const float* __restrict__ x1,
    const float* __restrict__ x2,
    const float* __restrict__ W0, const float* __restrict__ W1,
    const float* __restrict__ W2, int layer)
{
    __shared__ float Ws[C * C];
    __shared__ float xs[32 * C];
    __shared__ float zs[32][C + 1];

    int growBase = blockIdx.x * 32;
    const float* W; const float* xsrc;
    if (growBase < NR0) {
        W = W0;
        xsrc = layer ? (g_xA + (size_t)growBase * C) : (x0 + (size_t)growBase * C);
    } else if (growBase < NR0 + NR1) {
        W = W1;
        xsrc = layer ? (g_xA + (size_t)growBase * C) : (x1 + (size_t)(growBase - NR0) * C);
    } else {
        W = W2;
        xsrc = layer ? (g_xA + (size_t)growBase * C) : (x2 + (size_t)(growBase - NR0 - NR1) * C);
    }
    W += layer * C * C;

    int tid = threadIdx.x;
    for (int i = tid; i < C * C; i += 256) Ws[i] = W[i];
    for (int i = tid; i < 32 * C; i += 256) xs[i] = xsrc[i];
    __syncthreads();

    int c = tid & 63, rb = tid >> 6;
    #pragma unroll
    for (int rq = 0; rq < 8; rq++) {
        int r = rb * 8 + rq;
        float acc = 0.f;
        #pragma unroll
        for (int k = 0; k < C; k++) acc += xs[r * C + k] * Ws[k * C + c];
        zs[r][c] = acc * g_dinv[growBase + r];
    }
    __syncthreads();

    int c2 = tid >> 2, seg = tid & 3;
    size_t base = (size_t)c2 * NT + growBase + seg * 8;
    uint16_t hv[8], lv[8];
    #pragma unroll
    for (int j = 0; j < 8; j++) {
        float v = zs[seg * 8 + j][c2];
        uint16_t h = bf16_rn(v);
        hv[j] = h;
        lv[j] = bf16_rn(v - __uint_as_float((uint32_t)h << 16));
    }
    *(uint4*)&g_zhi[base] = *(uint4*)hv;
    *(uint4*)&g_zlo[base] = *(uint4*)lv;
}

// ============================================================
// mma.sync bf16x2 GEMM:  dst = relu(dinv .* (L @ z))
//   D = Ah*Bh + Ah*Bl   (A = bf16(L) only; B = z split hi/lo)
// BM=64, BN=64, BK=32, double-buffered, 128 thr = 4 warps (2m x 2n),
// warp tile m32n32. 256 CTAs, rank1 (long) first; 2 CTAs/SM.
// ============================================================
#define SA 40   // smem row pitch in halves
#define SB 40
#define AH_OFF 0
#define BH_OFF (64 * SA)
#define BL_OFF (64 * SA + C * SB)
#define STAGE_HALVES (64 * SA + 2 * C * SB)
#define GEMM_SMEM (2 * STAGE_HALVES * 2)   // bytes = 30720

__global__ __launch_bounds__(128, 2) void gemm_mma(
    const float* __restrict__ L0, const float* __restrict__ L1,
    const float* __restrict__ L2, int layer)
{
    extern __shared__ __align__(16) uint16_t sm[];

    // rank-1 CTAs first (longest jobs start in wave 1)
    int bx = blockIdx.x;
    const float* L; int N, lrowBase, growBase;
    if (bx < 128)      { L = L1; N = NR1; lrowBase = bx * 64;         growBase = NR0 + lrowBase; }
    else if (bx < 192) { L = L0; N = NR0; lrowBase = (bx - 128) * 64; growBase = lrowBase; }
    else               { L = L2; N = NR2; lrowBase = (bx - 192) * 64; growBase = NR0 + NR1 + lrowBase; }
    int zOff = growBase - lrowBase;
    int nc = N / 32;
    float* dst = layer ? g_xB : g_xA;

    int tid = threadIdx.x;
    int wid = tid >> 5, lane = tid & 31;
    int g = lane >> 2, tg = lane & 3;
    int wm = wid >> 1, wn = wid & 1;

    // ---- loader setup ----
    // A: 64 rows x 32 k -> 512 float4, 4 per thread (hi bf16 only)
    const float* aPtr[4]; int aSts[4];
    #pragma unroll
    for (int q = 0; q < 4; q++) {
        int idx = q * 128 + tid;
        int aRow = idx >> 3, aK4 = idx & 7;
        aPtr[q] = L + (size_t)(lrowBase + aRow) * N + aK4 * 4;
        aSts[q] = aRow * SA + aK4 * 4;
    }
    // B: 64 rows x 4 k8-groups -> 256 uint4 each for hi/lo, 2 per thread
    const uint16_t* bhPtr[2]; const uint16_t* blPtr[2]; int bSts[2];
    #pragma unroll
    for (int q = 0; q < 2; q++) {
        int idx = q * 128 + tid;
        int bRow = idx >> 2, bK8 = idx & 3;
        bhPtr[q] = g_zhi + (size_t)bRow * NT + zOff + bK8 * 8;
        blPtr[q] = g_zlo + (size_t)bRow * NT + zOff + bK8 * 8;
        bSts[q] = bRow * SB + bK8 * 8;
    }

    float acc[2][4][4];
    #pragma unroll
    for (int mt = 0; mt < 2; mt++)
        #pragma unroll
        for (int nt = 0; nt < 4; nt++)
            #pragma unroll
            for (int i = 0; i < 4; i++) acc[mt][nt][i] = 0.f;

    float4 ra[4]; uint4 rbh[2], rbl[2];

    // ---- prologue: chunk 0 -> smem stage 0; chunk 1 -> regs ----
    #pragma unroll
    for (int q = 0; q < 4; q++) ra[q] = *(const float4*)(aPtr[q]);
    #pragma unroll
    for (int q = 0; q < 2; q++) {
        rbh[q] = *(const uint4*)bhPtr[q];
        rbl[q] = *(const uint4*)blPtr[q];
    }
    {
        uint16_t* st = sm;
        #pragma unroll
        for (int q = 0; q < 4; q++) {
            float4 v = ra[q];
            *(uint2*)&st[AH_OFF + aSts[q]] =
                make_uint2(pack_bf16(v.x, v.y), pack_bf16(v.z, v.w));
        }
        #pragma unroll
        for (int q = 0; q < 2; q++) {
            *(uint4*)&st[BH_OFF + bSts[q]] = rbh[q];
            *(uint4*)&st[BL_OFF + bSts[q]] = rbl[q];
        }
    }
    if (nc > 1) {
        #pragma unroll
        for (int q = 0; q < 4; q++) ra[q] = *(const float4*)(aPtr[q] + 32);
        #pragma unroll
        for (int q = 0; q < 2; q++) {
            rbh[q] = *(const uint4*)(bhPtr[q] + 32);
            rbl[q] = *(const uint4*)(blPtr[q] + 32);
        }
    }
    __syncthreads();

    // ---- mainloop: one barrier per chunk ----
    for (int cI = 0; cI < nc; cI++) {
        if (cI + 1 < nc) {
            uint16_t* st = sm + ((cI + 1) & 1) * STAGE_HALVES;
            #pragma unroll
            for (int q = 0; q < 4; q++) {
                float4 v = ra[q];
                *(uint2*)&st[AH_OFF + aSts[q]] =
                    make_uint2(pack_bf16(v.x, v.y), pack_bf16(v.z, v.w));
            }
            #pragma unroll
            for (int q = 0; q < 2; q++) {
                *(uint4*)&st[BH_OFF + bSts[q]] = rbh[q];
                *(uint4*)&st[BL_OFF + bSts[q]] = rbl[q];
            }
        }
        if (cI + 2 < nc) {
            int k0 = (cI + 2) * 32;
            #pragma unroll
            for (int q = 0; q < 4; q++) ra[q] = *(const float4*)(aPtr[q] + k0);
            #pragma unroll
            for (int q = 0; q < 2; q++) {
                rbh[q] = *(const uint4*)(bhPtr[q] + k0);
                rbl[q] = *(const uint4*)(blPtr[q] + k0);
            }
        }

        const uint16_t* st = sm + (cI & 1) * STAGE_HALVES;
        #pragma unroll
        for (int ks = 0; ks < 2; ks++) {
            uint32_t ah[2][4];
            #pragma unroll
            for (int mt = 0; mt < 2; mt++) {
                int r0 = (wm * 32 + mt * 16 + g) * SA + ks * 16 + tg * 2;
                ah[mt][0] = *(const uint32_t*)&st[AH_OFF + r0];
                ah[mt][1] = *(const uint32_t*)&st[AH_OFF + r0 + 8 * SA];
                ah[mt][2] = *(const uint32_t*)&st[AH_OFF + r0 + 8];
                ah[mt][3] = *(const uint32_t*)&st[AH_OFF + r0 + 8 * SA + 8];
            }
            uint32_t bh[4][2], bl[4][2];
            #pragma unroll
            for (int nt = 0; nt < 4; nt++) {
                int b0 = (wn * 32 + nt * 8 + g) * SB + ks * 16 + tg * 2;
                bh[nt][0] = *(const uint32_t*)&st[BH_OFF + b0];
                bh[nt][1] = *(const uint32_t*)&st[BH_OFF + b0 + 8];
                bl[nt][0] = *(const uint32_t*)&st[BL_OFF + b0];
                bl[nt][1] = *(const uint32_t*)&st[BL_OFF + b0 + 8];
            }
            #pragma unroll
            for (int mt = 0; mt < 2; mt++)
                #pragma unroll
                for (int nt = 0; nt < 4; nt++) {
                    mma_bf16(acc[mt][nt], ah[mt], bh[nt]);
                    mma_bf16(acc[mt][nt], ah[mt], bl[nt]);
                }
        }
        __syncthreads();
    }

    // ---- epilogue: dinv row-scale + relu, write fp32 ----
    #pragma unroll
    for (int mt = 0; mt < 2; mt++) {
        int row0 = wm * 32 + mt * 16 + g;
        float dv0 = g_dinv[growBase + row0];
        float dv1 = g_dinv[growBase + row0 + 8];
        #pragma unroll
        for (int nt = 0; nt < 4; nt++) {
            int col = wn * 32 + nt * 8 + tg * 2;
            float* c = acc[mt][nt];
            float2 o0, o1;
            o0.x = fmaxf(c[0] * dv0, 0.f);
            o0.y = fmaxf(c[1] * dv0, 0.f);
            o1.x = fmaxf(c[2] * dv1, 0.f);
            o1.y = fmaxf(c[3] * dv1, 0.f);
            *(float2*)&dst[(size_t)(growBase + row0) * C + col]     = o0;
            *(float2*)&dst[(size_t)(growBase + row0 + 8) * C + col] = o1;
        }
    }
}

// ============================================================
// readout
// ============================================================
__global__ void zero_pooled_kernel() {
    int i = blockIdx.x * blockDim.x + threadIdx.x;
    if (i < 3 * NB * C) g_pooled[i] = 0.f;
}

__global__ void pool_kernel(const int* __restrict__ bel0,
                            const int* __restrict__ bel1,
                            const int* __restrict__ bel2) {
    int grow = blockIdx.x;
    int rank, lr;
    if (grow < NR0)            { rank = 0; lr = grow; }
    else if (grow < NR0 + NR1) { rank = 1; lr = grow - NR0; }
    else                       { rank = 2; lr = grow - NR0 - NR1; }
    const int* bel = (rank == 0) ? bel0 : (rank == 1 ? bel1 : bel2);
    int b = bel[lr];
    float v = g_xB[(size_t)grow * C + threadIdx.x];
    atomicAdd(&g_pooled[rank * NB * C + b * C + threadIdx.x], v);
}

__global__ void out_kernel(const float* __restrict__ Wr0, const float* __restrict__ br0,
                           const float* __restrict__ Wr1, const float* __restrict__ br1,
                           const float* __restrict__ Wr2, const float* __restrict__ br2,
                           float* __restrict__ out) {
    int b = blockIdx.x;
    int o = threadIdx.x;
    float acc = br0[o] + br1[o] + br2[o];
    const float* Wrs[3] = {Wr0, Wr1, Wr2};
    #pragma unroll
    for (int r = 0; r < 3; r++) {
        const float* Wr = Wrs[r];
        const float* p  = &g_pooled[r * NB * C + b * C];
        #pragma unroll 8
        for (int c = 0; c < C; c++) acc += p[c] * Wr[c * OUTC + o];
    }
    out[b * OUTC + o] = acc;
}

// ============================================================
extern "C" void kernel_launch(void* const* d_in, const int* in_sizes, int n_in,
                              void* d_out, int out_size) {
    const float* x0  = (const float*)d_in[0];
    const float* x1  = (const float*)d_in[1];
    const float* x2  = (const float*)d_in[2];
    const float* L0  = (const float*)d_in[3];
    const float* L1  = (const float*)d_in[4];
    const float* L2  = (const float*)d_in[5];
    const int*   bel0 = (const int*)d_in[6];
    const int*   bel1 = (const int*)d_in[7];
    const int*   bel2 = (const int*)d_in[8];
    const float* W0  = (const float*)d_in[9];
    const float* W1  = (const float*)d_in[10];
    const float* W2  = (const float*)d_in[11];
    const float* Wr0 = (const float*)d_in[12];
    const float* br0 = (const float*)d_in[13];
    const float* Wr1 = (const float*)d_in[14];
    const float* br1 = (const float*)d_in[15];
    const float* Wr2 = (const float*)d_in[16];
    const float* br2 = (const float*)d_in[17];

    cudaFuncSetAttribute(gemm_mma, cudaFuncAttributeMaxDynamicSharedMemorySize, GEMM_SMEM);

    dinv_kernel<<<NT, 128>>>(L0, L1, L2);

    for (int layer = 0; layer < 2; layer++) {
        xw_kernel<<<NT / 32, 256>>>(x0, x1, x2, W0, W1, W2, layer);
        gemm_mma<<<256, 128, GEMM_SMEM>>>(L0, L1, L2, layer);
    }

    zero_pooled_kernel<<<(3 * NB * C + 255) / 256, 256>>>();
    pool_kernel<<<NT, 64>>>(bel0, bel1, bel2);
    out_kernel<<<NB, OUTC>>>(Wr0, br0, Wr1, br1, Wr2, br2, (float*)d_out);
}

// round 7
// speedup vs baseline: 1.0664x; 1.0118x over previous
#include <cuda_runtime.h>
#include <cstdint>

#define NR0 4096
#define NR1 8192
#define NR2 4096
#define NT  16384     // NR0+NR1+NR2
#define C   64
#define OUTC 32
#define NB  64

// ---- scratch (device globals; no allocation allowed) ----
__device__ float    g_dinv[NT];
__device__ uint16_t g_zhi[C * NT];    // bf16 hi of z^T [C][NT] (K-major B operand)
__device__ uint16_t g_zlo[C * NT];    // bf16 lo
__device__ float    g_xA[NT * C];
__device__ float    g_xB[NT * C];
__device__ float    g_pooled[3 * NB * C];

// ============================================================
// helpers
// ============================================================
__device__ __forceinline__ uint32_t pack_bf16(float lo, float hi) {
    uint32_t r;
    asm("cvt.rn.bf16x2.f32 %0, %1, %2;" : "=r"(r) : "f"(hi), "f"(lo));
    return r;
}
__device__ __forceinline__ uint16_t bf16_rn(float x) {
    uint16_t r;
    asm("cvt.rn.bf16.f32 %0, %1;" : "=h"(r) : "f"(x));
    return r;
}
__device__ __forceinline__ void mma_bf16(float* c, const uint32_t* a, const uint32_t* b) {
    asm volatile("mma.sync.aligned.m16n8k16.row.col.f32.bf16.bf16.f32 "
        "{%0,%1,%2,%3}, {%4,%5,%6,%7}, {%8,%9}, {%0,%1,%2,%3};"
        : "+f"(c[0]), "+f"(c[1]), "+f"(c[2]), "+f"(c[3])
        : "r"(a[0]), "r"(a[1]), "r"(a[2]), "r"(a[3]), "r"(b[0]), "r"(b[1]));
}
__device__ __forceinline__ void ldsm_x4(uint32_t& r0, uint32_t& r1, uint32_t& r2,
                                        uint32_t& r3, uint32_t addr) {
    asm volatile("ldmatrix.sync.aligned.m8n8.x4.shared.b16 {%0,%1,%2,%3}, [%4];"
                 : "=r"(r0), "=r"(r1), "=r"(r2), "=r"(r3) : "r"(addr));
}

// ============================================================
// dinv[i] = rsqrt(rowsum |L_i|), 0 if rowsum == 0
// ============================================================
__global__ void dinv_kernel(const float* __restrict__ L0,
                            const float* __restrict__ L1,
                            const float* __restrict__ L2) {
    int grow = blockIdx.x;
    const float* L; int N; int lr;
    if (grow < NR0)             { L = L0; N = NR0; lr = grow; }
    else if (grow < NR0 + NR1)  { L = L1; N = NR1; lr = grow - NR0; }
    else                        { L = L2; N = NR2; lr = grow - NR0 - NR1; }

    const float4* row = (const float4*)(L + (size_t)lr * N);
    int n4 = N >> 2;
    float s = 0.f;
    for (int j = threadIdx.x; j < n4; j += blockDim.x) {
        float4 v = row[j];
        s += fabsf(v.x) + fabsf(v.y) + fabsf(v.z) + fabsf(v.w);
    }
    __shared__ float red[4];
    for (int o = 16; o > 0; o >>= 1) s += __shfl_down_sync(0xffffffffu, s, o);
    if ((threadIdx.x & 31) == 0) red[threadIdx.x >> 5] = s;
    __syncthreads();
    if (threadIdx.x == 0) {
        float d = red[0] + red[1] + red[2] + red[3];
        g_dinv[grow] = (d != 0.f) ? rsqrtf(d) : 0.f;
    }
}

// ============================================================
// z = dinv .* (x @ W[layer]); emit bf16 hi/lo transposed [C][NT]
// ============================================================
__global__ __launch_bounds__(256) void xw_kernel(
    const float* __restrict__ x0, const float* __restrict__ x1,
    const float* __restrict__ x2,
    const float* __restrict__ W0, const float* __restrict__ W1,
    const float* __restrict__ W2, int layer)
{
    __shared__ float Ws[C * C];
    __shared__ float xs[32 * C];
    __shared__ float zs[32][C + 1];

    int growBase = blockIdx.x * 32;
    const float* W; const float* xsrc;
    if (growBase < NR0) {
        W = W0;
        xsrc = layer ? (g_xA + (size_t)growBase * C) : (x0 + (size_t)growBase * C);
    } else if (growBase < NR0 + NR1) {
        W = W1;
        xsrc = layer ? (g_xA + (size_t)growBase * C) : (x1 + (size_t)(growBase - NR0) * C);
    } else {
        W = W2;
        xsrc = layer ? (g_xA + (size_t)growBase * C) : (x2 + (size_t)(growBase - NR0 - NR1) * C);
    }
    W += layer * C * C;

    int tid = threadIdx.x;
    for (int i = tid; i < C * C; i += 256) Ws[i] = W[i];
    for (int i = tid; i < 32 * C; i += 256) xs[i] = xsrc[i];
    __syncthreads();

    int c = tid & 63, rb = tid >> 6;
    #pragma unroll
    for (int rq = 0; rq < 8; rq++) {
        int r = rb * 8 + rq;
        float acc = 0.f;
        #pragma unroll
        for (int k = 0; k < C; k++) acc += xs[r * C + k] * Ws[k * C + c];
        zs[r][c] = acc * g_dinv[growBase + r];
    }
    __syncthreads();

    int c2 = tid >> 2, seg = tid & 3;
    size_t base = (size_t)c2 * NT + growBase + seg * 8;
    uint16_t hv[8], lv[8];
    #pragma unroll
    for (int j = 0; j < 8; j++) {
        float v = zs[seg * 8 + j][c2];
        uint16_t h = bf16_rn(v);
        hv[j] = h;
        lv[j] = bf16_rn(v - __uint_as_float((uint32_t)h << 16));
    }
    *(uint4*)&g_zhi[base] = *(uint4*)hv;
    *(uint4*)&g_zlo[base] = *(uint4*)lv;
}

// ============================================================
// mma.sync bf16x2 GEMM with ldmatrix fragment loads:
//   dst = relu(dinv .* (L @ z)),  D = Ah*Bh + Ah*Bl
// BM=64, BN=64, BK=32, double-buffered, 128 thr = 4 warps (2m x 2n),
// warp tile m32n32. 256 CTAs, rank1 first; 3 CTAs/SM.
// ============================================================
#define SA 40   // smem row pitch in halves
#define SB 40
#define AH_OFF 0
#define BH_OFF (64 * SA)
#define BL_OFF (64 * SA + C * SB)
#define STAGE_HALVES (64 * SA + 2 * C * SB)
#define GEMM_SMEM (2 * STAGE_HALVES * 2)   // bytes = 30720

__global__ __launch_bounds__(128, 3) void gemm_mma(
    const float* __restrict__ L0, const float* __restrict__ L1,
    const float* __restrict__ L2, int layer)
{
    extern __shared__ __align__(16) uint16_t sm[];

    // rank-1 CTAs first (longest jobs start in wave 1)
    int bx = blockIdx.x;
    const float* L; int N, lrowBase, growBase;
    if (bx < 128)      { L = L1; N = NR1; lrowBase = bx * 64;         growBase = NR0 + lrowBase; }
    else if (bx < 192) { L = L0; N = NR0; lrowBase = (bx - 128) * 64; growBase = lrowBase; }
    else               { L = L2; N = NR2; lrowBase = (bx - 192) * 64; growBase = NR0 + NR1 + lrowBase; }
    int zOff = growBase - lrowBase;
    int nc = N / 32;
    float* dst = layer ? g_xB : g_xA;

    int tid = threadIdx.x;
    int wid = tid >> 5, lane = tid & 31;
    int g = lane >> 2, tg = lane & 3;
    int wm = wid >> 1, wn = wid & 1;

    uint32_t smBase = (uint32_t)__cvta_generic_to_shared(sm);

    // ---- ldmatrix lane-relative byte offsets (within a stage) ----
    // A x4 (per mt, per ks): matrices [rows 0-7,k0-7][rows8-15,k0-7][rows0-7,k8-15][rows8-15,k8-15]
    //   lane row = base + (lane&15), col halves = (lane&16) ? 8 : 0
    uint32_t aLdsm[2][2];
    #pragma unroll
    for (int mt = 0; mt < 2; mt++)
        #pragma unroll
        for (int ks = 0; ks < 2; ks++) {
            int row = wm * 32 + mt * 16 + (lane & 15);
            int col = ks * 16 + ((lane & 16) ? 8 : 0);
            aLdsm[mt][ks] = 2u * (AH_OFF + row * SA + col);
        }
    // B x4 (per n-pair p, per ks): matrices [n0-7,k0-7][n0-7,k8-15][n8-15,k0-7][n8-15,k8-15]
    //   lane row = base + (lane&7) + ((lane&16)>>1), col halves = (lane&8) ? 8 : 0
    uint32_t bLdsmRel[2][2];   // relative to BH_OFF/BL_OFF
    #pragma unroll
    for (int p = 0; p < 2; p++)
        #pragma unroll
        for (int ks = 0; ks < 2; ks++) {
            int row = wn * 32 + p * 16 + (lane & 7) + ((lane & 16) >> 1);
            int col = ks * 16 + ((lane & 8) ? 8 : 0);
            bLdsmRel[p][ks] = 2u * (row * SB + col);
        }

    // ---- loader setup ----
    const float* aPtr[4]; int aSts[4];
    #pragma unroll
    for (int q = 0; q < 4; q++) {
        int idx = q * 128 + tid;
        int aRow = idx >> 3, aK4 = idx & 7;
        aPtr[q] = L + (size_t)(lrowBase + aRow) * N + aK4 * 4;
        aSts[q] = aRow * SA + aK4 * 4;
    }
    const uint16_t* bhPtr[2]; const uint16_t* blPtr[2]; int bSts[2];
    #pragma unroll
    for (int q = 0; q < 2; q++) {
        int idx = q * 128 + tid;
        int bRow = idx >> 2, bK8 = idx & 3;
        bhPtr[q] = g_zhi + (size_t)bRow * NT + zOff + bK8 * 8;
        blPtr[q] = g_zlo + (size_t)bRow * NT + zOff + bK8 * 8;
        bSts[q] = bRow * SB + bK8 * 8;
    }

    float acc[2][4][4];
    #pragma unroll
    for (int mt = 0; mt < 2; mt++)
        #pragma unroll
        for (int nt = 0; nt < 4; nt++)
            #pragma unroll
            for (int i = 0; i < 4; i++) acc[mt][nt][i] = 0.f;

    float4 ra[4]; uint4 rbh[2], rbl[2];

    // ---- prologue: chunk 0 -> smem stage 0; chunk 1 -> regs ----
    #pragma unroll
    for (int q = 0; q < 4; q++) ra[q] = *(const float4*)(aPtr[q]);
    #pragma unroll
    for (int q = 0; q < 2; q++) {
        rbh[q] = *(const uint4*)bhPtr[q];
        rbl[q] = *(const uint4*)blPtr[q];
    }
    {
        uint16_t* st = sm;
        #pragma unroll
        for (int q = 0; q < 4; q++) {
            float4 v = ra[q];
            *(uint2*)&st[AH_OFF + aSts[q]] =
                make_uint2(pack_bf16(v.x, v.y), pack_bf16(v.z, v.w));
        }
        #pragma unroll
        for (int q = 0; q < 2; q++) {
            *(uint4*)&st[BH_OFF + bSts[q]] = rbh[q];
            *(uint4*)&st[BL_OFF + bSts[q]] = rbl[q];
        }
    }
    if (nc > 1) {
        #pragma unroll
        for (int q = 0; q < 4; q++) ra[q] = *(const float4*)(aPtr[q] + 32);
        #pragma unroll
        for (int q = 0; q < 2; q++) {
            rbh[q] = *(const uint4*)(bhPtr[q] + 32);
            rbl[q] = *(const uint4*)(blPtr[q] + 32);
        }
    }
    __syncthreads();

    // ---- mainloop: one barrier per chunk ----
    for (int cI = 0; cI < nc; cI++) {
        if (cI + 1 < nc) {
            uint16_t* st = sm + ((cI + 1) & 1) * STAGE_HALVES;
            #pragma unroll
            for (int q = 0; q < 4; q++) {
                float4 v = ra[q];
                *(uint2*)&st[AH_OFF + aSts[q]] =
                    make_uint2(pack_bf16(v.x, v.y), pack_bf16(v.z, v.w));
            }
            #pragma unroll
            for (int q = 0; q < 2; q++) {
                *(uint4*)&st[BH_OFF + bSts[q]] = rbh[q];
                *(uint4*)&st[BL_OFF + bSts[q]] = rbl[q];
            }
        }
        if (cI + 2 < nc) {
            int k0 = (cI + 2) * 32;
            #pragma unroll
            for (int q = 0; q < 4; q++) ra[q] = *(const float4*)(aPtr[q] + k0);
            #pragma unroll
            for (int q = 0; q < 2; q++) {
                rbh[q] = *(const uint4*)(bhPtr[q] + k0);
                rbl[q] = *(const uint4*)(blPtr[q] + k0);
            }
        }

        uint32_t stage = smBase + ((cI & 1) ? STAGE_HALVES * 2u : 0u);
        #pragma unroll
        for (int ks = 0; ks < 2; ks++) {
            uint32_t ah[2][4];
            #pragma unroll
            for (int mt = 0; mt < 2; mt++)
                ldsm_x4(ah[mt][0], ah[mt][1], ah[mt][2], ah[mt][3],
                        stage + aLdsm[mt][ks]);
            uint32_t bh[4][2], bl[4][2];
            #pragma unroll
            for (int p = 0; p < 2; p++) {
                ldsm_x4(bh[p * 2][0], bh[p * 2][1], bh[p * 2 + 1][0], bh[p * 2 + 1][1],
                        stage + 2u * BH_OFF + bLdsmRel[p][ks]);
                ldsm_x4(bl[p * 2][0], bl[p * 2][1], bl[p * 2 + 1][0], bl[p * 2 + 1][1],
                        stage + 2u * BL_OFF + bLdsmRel[p][ks]);
            }
            #pragma unroll
            for (int mt = 0; mt < 2; mt++)
                #pragma unroll
                for (int nt = 0; nt < 4; nt++) {
                    mma_bf16(acc[mt][nt], ah[mt], bh[nt]);
                    mma_bf16(acc[mt][nt], ah[mt], bl[nt]);
                }
        }
        __syncthreads();
    }

    // ---- epilogue: dinv row-scale + relu, write fp32 ----
    #pragma unroll
    for (int mt = 0; mt < 2; mt++) {
        int row0 = wm * 32 + mt * 16 + g;
        float dv0 = g_dinv[growBase + row0];
        float dv1 = g_dinv[growBase + row0 + 8];
        #pragma unroll
        for (int nt = 0; nt < 4; nt++) {
            int col = wn * 32 + nt * 8 + tg * 2;
            float* c = acc[mt][nt];
            float2 o0, o1;
            o0.x = fmaxf(c[0] * dv0, 0.f);
            o0.y = fmaxf(c[1] * dv0, 0.f);
            o1.x = fmaxf(c[2] * dv1, 0.f);
            o1.y = fmaxf(c[3] * dv1, 0.f);
            *(float2*)&dst[(size_t)(growBase + row0) * C + col]     = o0;
            *(float2*)&dst[(size_t)(growBase + row0 + 8) * C + col] = o1;
        }
    }
}

// ============================================================
// readout
// ============================================================
__global__ void zero_pooled_kernel() {
    int i = blockIdx.x * blockDim.x + threadIdx.x;
    if (i < 3 * NB * C) g_pooled[i] = 0.f;
}

__global__ void pool_kernel(const int* __restrict__ bel0,
                            const int* __restrict__ bel1,
                            const int* __restrict__ bel2) {
    int grow = blockIdx.x;
    int rank, lr;
    if (grow < NR0)            { rank = 0; lr = grow; }
    else if (grow < NR0 + NR1) { rank = 1; lr = grow - NR0; }
    else                       { rank = 2; lr = grow - NR0 - NR1; }
    const int* bel = (rank == 0) ? bel0 : (rank == 1 ? bel1 : bel2);
    int b = bel[lr];
    float v = g_xB[(size_t)grow * C + threadIdx.x];
    atomicAdd(&g_pooled[rank * NB * C + b * C + threadIdx.x], v);
}

__global__ void out_kernel(const float* __restrict__ Wr0, const float* __restrict__ br0,
                           const float* __restrict__ Wr1, const float* __restrict__ br1,
                           const float* __restrict__ Wr2, const float* __restrict__ br2,
                           float* __restrict__ out) {
    int b = blockIdx.x;
    int o = threadIdx.x;
    float acc = br0[o] + br1[o] + br2[o];
    const float* Wrs[3] = {Wr0, Wr1, Wr2};
    #pragma unroll
    for (int r = 0; r < 3; r++) {
        const float* Wr = Wrs[r];
        const float* p  = &g_pooled[r * NB * C + b * C];
        #pragma unroll 8
        for (int c = 0; c < C; c++) acc += p[c] * Wr[c * OUTC + o];
    }
    out[b * OUTC + o] = acc;
}

// ============================================================
extern "C" void kernel_launch(void* const* d_in, const int* in_sizes, int n_in,
                              void* d_out, int out_size) {
    const float* x0  = (const float*)d_in[0];
    const float* x1  = (const float*)d_in[1];
    const float* x2  = (const float*)d_in[2];
    const float* L0  = (const float*)d_in[3];
    const float* L1  = (const float*)d_in[4];
    const float* L2  = (const float*)d_in[5];
    const int*   bel0 = (const int*)d_in[6];
    const int*   bel1 = (const int*)d_in[7];
    const int*   bel2 = (const int*)d_in[8];
    const float* W0  = (const float*)d_in[9];
    const float* W1  = (const float*)d_in[10];
    const float* W2  = (const float*)d_in[11];
    const float* Wr0 = (const float*)d_in[12];
    const float* br0 = (const float*)d_in[13];
    const float* Wr1 = (const float*)d_in[14];
    const float* br1 = (const float*)d_in[15];
    const float* Wr2 = (const float*)d_in[16];
    const float* br2 = (const float*)d_in[17];

    cudaFuncSetAttribute(gemm_mma, cudaFuncAttributeMaxDynamicSharedMemorySize, GEMM_SMEM);

    dinv_kernel<<<NT, 128>>>(L0, L1, L2);

    for (int layer = 0; layer < 2; layer++) {
        xw_kernel<<<NT / 32, 256>>>(x0, x1, x2, W0, W1, W2, layer);
        gemm_mma<<<256, 128, GEMM_SMEM>>>(L0, L1, L2, layer);
    }

    zero_pooled_kernel<<<(3 * NB * C + 255) / 256, 256>>>();
    pool_kernel<<<NT, 64>>>(bel0, bel1, bel2);
    out_kernel<<<NB, OUTC>>>(Wr0, br0, Wr1, br1, Wr2, br2, (float*)d_out);
}

// round 8
// speedup vs baseline: 1.0872x; 1.0195x over previous
#include <cuda_runtime.h>
#include <cstdint>

#define NR0 4096
#define NR1 8192
#define NR2 4096
#define NT  16384     // NR0+NR1+NR2
#define C   64
#define OUTC 32
#define NB  64

// ---- scratch (device globals; no allocation allowed) ----
__device__ float    g_dinv[NT];
__device__ uint16_t g_zhi[C * NT];    // bf16 hi of z^T [C][NT] (K-major B operand)
__device__ uint16_t g_zlo[C * NT];    // bf16 lo
__device__ float    g_xA[NT * C];
__device__ float    g_xB[NT * C];
__device__ float    g_pooled[3 * NB * C];

// ============================================================
// helpers
// ============================================================
__device__ __forceinline__ uint32_t pack_bf16(float lo, float hi) {
    uint32_t r;
    asm("cvt.rn.bf16x2.f32 %0, %1, %2;" : "=r"(r) : "f"(hi), "f"(lo));
    return r;
}
__device__ __forceinline__ uint16_t bf16_rn(float x) {
    uint16_t r;
    asm("cvt.rn.bf16.f32 %0, %1;" : "=h"(r) : "f"(x));
    return r;
}
__device__ __forceinline__ void mma_bf16(float* c, const uint32_t* a, const uint32_t* b) {
    asm volatile("mma.sync.aligned.m16n8k16.row.col.f32.bf16.bf16.f32 "
        "{%0,%1,%2,%3}, {%4,%5,%6,%7}, {%8,%9}, {%0,%1,%2,%3};"
        : "+f"(c[0]), "+f"(c[1]), "+f"(c[2]), "+f"(c[3])
        : "r"(a[0]), "r"(a[1]), "r"(a[2]), "r"(a[3]), "r"(b[0]), "r"(b[1]));
}
__device__ __forceinline__ void ldsm_x4(uint32_t& r0, uint32_t& r1, uint32_t& r2,
                                        uint32_t& r3, uint32_t addr) {
    asm volatile("ldmatrix.sync.aligned.m8n8.x4.shared.b16 {%0,%1,%2,%3}, [%4];"
                 : "=r"(r0), "=r"(r1), "=r"(r2), "=r"(r3) : "r"(addr));
}

// ============================================================
// dinv[i] = rsqrt(rowsum |L_i|), 0 if rowsum == 0
// ============================================================
__global__ void dinv_kernel(const float* __restrict__ L0,
                            const float* __restrict__ L1,
                            const float* __restrict__ L2) {
    int grow = blockIdx.x;
    const float* L; int N; int lr;
    if (grow < NR0)             { L = L0; N = NR0; lr = grow; }
    else if (grow < NR0 + NR1)  { L = L1; N = NR1; lr = grow - NR0; }
    else                        { L = L2; N = NR2; lr = grow - NR0 - NR1; }

    const float4* row = (const float4*)(L + (size_t)lr * N);
    int n4 = N >> 2;
    float s = 0.f;
    for (int j = threadIdx.x; j < n4; j += blockDim.x) {
        float4 v = row[j];
        s += fabsf(v.x) + fabsf(v.y) + fabsf(v.z) + fabsf(v.w);
    }
    __shared__ float red[4];
    for (int o = 16; o > 0; o >>= 1) s += __shfl_down_sync(0xffffffffu, s, o);
    if ((threadIdx.x & 31) == 0) red[threadIdx.x >> 5] = s;
    __syncthreads();
    if (threadIdx.x == 0) {
        float d = red[0] + red[1] + red[2] + red[3];
        g_dinv[grow] = (d != 0.f) ? rsqrtf(d) : 0.f;
    }
}

// ============================================================
// z = dinv .* (x @ W[layer]); emit bf16 hi/lo transposed [C][NT]
// ============================================================
__global__ __launch_bounds__(256) void xw_kernel(
    const float* __restrict__ x0, const float* __restrict__ x1,
    const float* __restrict__ x2,
    const float* __restrict__ W0, const float* __restrict__ W1,
    const float* __restrict__ W2, int layer)
{
    __shared__ float Ws[C * C];
    __shared__ float xs[32 * C];
    __shared__ float zs[32][C + 1];

    int growBase = blockIdx.x * 32;
    const float* W; const float* xsrc;
    if (growBase < NR0) {
        W = W0;
        xsrc = layer ? (g_xA + (size_t)growBase * C) : (x0 + (size_t)growBase * C);
    } else if (growBase < NR0 + NR1) {
        W = W1;
        xsrc = layer ? (g_xA + (size_t)growBase * C) : (x1 + (size_t)(growBase - NR0) * C);
    } else {
        W = W2;
        xsrc = layer ? (g_xA + (size_t)growBase * C) : (x2 + (size_t)(growBase - NR0 - NR1) * C);
    }
    W += layer * C * C;

    int tid = threadIdx.x;
    for (int i = tid; i < C * C; i += 256) Ws[i] = W[i];
    for (int i = tid; i < 32 * C; i += 256) xs[i] = xsrc[i];
    __syncthreads();

    int c = tid & 63, rb = tid >> 6;
    #pragma unroll
    for (int rq = 0; rq < 8; rq++) {
        int r = rb * 8 + rq;
        float acc = 0.f;
        #pragma unroll
        for (int k = 0; k < C; k++) acc += xs[r * C + k] * Ws[k * C + c];
        zs[r][c] = acc * g_dinv[growBase + r];
    }
    __syncthreads();

    int c2 = tid >> 2, seg = tid & 3;
    size_t base = (size_t)c2 * NT + growBase + seg * 8;
    uint16_t hv[8], lv[8];
    #pragma unroll
    for (int j = 0; j < 8; j++) {
        float v = zs[seg * 8 + j][c2];
        uint16_t h = bf16_rn(v);
        hv[j] = h;
        lv[j] = bf16_rn(v - __uint_as_float((uint32_t)h << 16));
    }
    *(uint4*)&g_zhi[base] = *(uint4*)hv;
    *(uint4*)&g_zlo[base] = *(uint4*)lv;
}

// ============================================================
// mma.sync bf16x2 GEMM with ldmatrix:
//   dst = relu(dinv .* (L @ z)),  D = Ah*Bh + Ah*Bl
// BM=64, BN=64, BK=32, double-buffered.
// 256 thr = 8 warps (2m x 4n), warp tile m32n16 -> ~3.4 warps/SMSP.
// 256 CTAs, rank1 (long) first; 2 CTAs/SM.
// ============================================================
#define SA 40   // smem row pitch in halves
#define SB 40
#define AH_OFF 0
#define BH_OFF (64 * SA)
#define BL_OFF (64 * SA + C * SB)
#define STAGE_HALVES (64 * SA + 2 * C * SB)
#define GEMM_SMEM (2 * STAGE_HALVES * 2)   // bytes = 30720

__global__ __launch_bounds__(256, 2) void gemm_mma(
    const float* __restrict__ L0, const float* __restrict__ L1,
    const float* __restrict__ L2, int layer)
{
    extern __shared__ __align__(16) uint16_t sm[];

    // rank-1 CTAs first (longest jobs start in wave 1)
    int bx = blockIdx.x;
    const float* L; int N, lrowBase, growBase;
    if (bx < 128)      { L = L1; N = NR1; lrowBase = bx * 64;         growBase = NR0 + lrowBase; }
    else if (bx < 192) { L = L0; N = NR0; lrowBase = (bx - 128) * 64; growBase = lrowBase; }
    else               { L = L2; N = NR2; lrowBase = (bx - 192) * 64; growBase = NR0 + NR1 + lrowBase; }
    int zOff = growBase - lrowBase;
    int nc = N / 32;
    float* dst = layer ? g_xB : g_xA;

    int tid = threadIdx.x;
    int wid = tid >> 5, lane = tid & 31;
    int g = lane >> 2, tg = lane & 3;
    int wm = wid >> 2, wn = wid & 3;     // 2m x 4n warp grid, tile m32n16

    uint32_t smBase = (uint32_t)__cvta_generic_to_shared(sm);

    // ---- ldmatrix lane-relative byte offsets (within a stage) ----
    // A x4 (per mt, per ks): lane row = wm*32+mt*16+(lane&15), col = ks*16 + ((lane&16)?8:0)
    uint32_t aLdsm[2][2];
    #pragma unroll
    for (int mt = 0; mt < 2; mt++)
        #pragma unroll
        for (int ks = 0; ks < 2; ks++) {
            int row = wm * 32 + mt * 16 + (lane & 15);
            int col = ks * 16 + ((lane & 16) ? 8 : 0);
            aLdsm[mt][ks] = 2u * (AH_OFF + row * SA + col);
        }
    // B x4 (per ks): 16 n-rows per warp. lane row = wn*16 + (lane&7) + ((lane&16)>>1),
    // col = ks*16 + ((lane&8)?8:0). Outputs: [n0-7,k0][n0-7,k8][n8-15,k0][n8-15,k8]
    uint32_t bLdsmRel[2];   // relative to BH_OFF/BL_OFF (byte offsets)
    #pragma unroll
    for (int ks = 0; ks < 2; ks++) {
        int row = wn * 16 + (lane & 7) + ((lane & 16) >> 1);
        int col = ks * 16 + ((lane & 8) ? 8 : 0);
        bLdsmRel[ks] = 2u * (row * SB + col);
    }

    // ---- loader setup ----
    // A: 64 rows x 32 k -> 512 float4, 2 per thread
    const float* aPtr[2]; int aSts[2];
    #pragma unroll
    for (int q = 0; q < 2; q++) {
        int idx = q * 256 + tid;
        int aRow = idx >> 3, aK4 = idx & 7;
        aPtr[q] = L + (size_t)(lrowBase + aRow) * N + aK4 * 4;
        aSts[q] = aRow * SA + aK4 * 4;
    }
    // B: 64 rows x 4 k8-groups -> 256 uint4 each for hi/lo, 1 each per thread
    int bRow = tid >> 2, bK8 = tid & 3;
    const uint16_t* bhPtr = g_zhi + (size_t)bRow * NT + zOff + bK8 * 8;
    const uint16_t* blPtr = g_zlo + (size_t)bRow * NT + zOff + bK8 * 8;
    int bSts = bRow * SB + bK8 * 8;

    float acc[2][2][4];
    #pragma unroll
    for (int mt = 0; mt < 2; mt++)
        #pragma unroll
        for (int nt = 0; nt < 2; nt++)
            #pragma unroll
            for (int i = 0; i < 4; i++) acc[mt][nt][i] = 0.f;

    float4 ra[2]; uint4 rbh, rbl;

    // ---- prologue: chunk 0 -> smem stage 0; chunk 1 -> regs ----
    #pragma unroll
    for (int q = 0; q < 2; q++) ra[q] = *(const float4*)(aPtr[q]);
    rbh = *(const uint4*)bhPtr;
    rbl = *(const uint4*)blPtr;
    {
        uint16_t* st = sm;
        #pragma unroll
        for (int q = 0; q < 2; q++) {
            float4 v = ra[q];
            *(uint2*)&st[AH_OFF + aSts[q]] =
                make_uint2(pack_bf16(v.x, v.y), pack_bf16(v.z, v.w));
        }
        *(uint4*)&st[BH_OFF + bSts] = rbh;
        *(uint4*)&st[BL_OFF + bSts] = rbl;
    }
    if (nc > 1) {
        #pragma unroll
        for (int q = 0; q < 2; q++) ra[q] = *(const float4*)(aPtr[q] + 32);
        rbh = *(const uint4*)(bhPtr + 32);
        rbl = *(const uint4*)(blPtr + 32);
    }
    __syncthreads();

    // ---- mainloop: one barrier per chunk ----
    for (int cI = 0; cI < nc; cI++) {
        if (cI + 1 < nc) {
            uint16_t* st = sm + ((cI + 1) & 1) * STAGE_HALVES;
            #pragma unroll
            for (int q = 0; q < 2; q++) {
                float4 v = ra[q];
                *(uint2*)&st[AH_OFF + aSts[q]] =
                    make_uint2(pack_bf16(v.x, v.y), pack_bf16(v.z, v.w));
            }
            *(uint4*)&st[BH_OFF + bSts] = rbh;
            *(uint4*)&st[BL_OFF + bSts] = rbl;
        }
        if (cI + 2 < nc) {
            int k0 = (cI + 2) * 32;
            #pragma unroll
            for (int q = 0; q < 2; q++) ra[q] = *(const float4*)(aPtr[q] + k0);
            rbh = *(const uint4*)(bhPtr + k0);
            rbl = *(const uint4*)(blPtr + k0);
        }

        uint32_t stage = smBase + ((cI & 1) ? STAGE_HALVES * 2u : 0u);
        #pragma unroll
        for (int ks = 0; ks < 2; ks++) {
            uint32_t ah[2][4];
            #pragma unroll
            for (int mt = 0; mt < 2; mt++)
                ldsm_x4(ah[mt][0], ah[mt][1], ah[mt][2], ah[mt][3],
                        stage + aLdsm[mt][ks]);
            uint32_t bh[2][2], bl[2][2];
            ldsm_x4(bh[0][0], bh[0][1], bh[1][0], bh[1][1],
                    stage + 2u * BH_OFF + bLdsmRel[ks]);
            ldsm_x4(bl[0][0], bl[0][1], bl[1][0], bl[1][1],
                    stage + 2u * BL_OFF + bLdsmRel[ks]);
            #pragma unroll
            for (int mt = 0; mt < 2; mt++)
                #pragma unroll
                for (int nt = 0; nt < 2; nt++) {
                    mma_bf16(acc[mt][nt], ah[mt], bh[nt]);
                    mma_bf16(acc[mt][nt], ah[mt], bl[nt]);
                }
        }
        __syncthreads();
    }

    // ---- epilogue: dinv row-scale + relu, write fp32 ----
    #pragma unroll
    for (int mt = 0; mt < 2; mt++) {
        int row0 = wm * 32 + mt * 16 + g;
        float dv0 = g_dinv[growBase + row0];
        float dv1 = g_dinv[growBase + row0 + 8];
        #pragma unroll
        for (int nt = 0; nt < 2; nt++) {
            int col = wn * 16 + nt * 8 + tg * 2;
            float* c = acc[mt][nt];
            float2 o0, o1;
            o0.x = fmaxf(c[0] * dv0, 0.f);
            o0.y = fmaxf(c[1] * dv0, 0.f);
            o1.x = fmaxf(c[2] * dv1, 0.f);
            o1.y = fmaxf(c[3] * dv1, 0.f);
            *(float2*)&dst[(size_t)(growBase + row0) * C + col]     = o0;
            *(float2*)&dst[(size_t)(growBase + row0 + 8) * C + col] = o1;
        }
    }
}

// ============================================================
// readout
// ============================================================
__global__ void zero_pooled_kernel() {
    int i = blockIdx.x * blockDim.x + threadIdx.x;
    if (i < 3 * NB * C) g_pooled[i] = 0.f;
}

__global__ void pool_kernel(const int* __restrict__ bel0,
                            const int* __restrict__ bel1,
                            const int* __restrict__ bel2) {
    int grow = blockIdx.x;
    int rank, lr;
    if (grow < NR0)            { rank = 0; lr = grow; }
    else if (grow < NR0 + NR1) { rank = 1; lr = grow - NR0; }
    else                       { rank = 2; lr = grow - NR0 - NR1; }
    const int* bel = (rank == 0) ? bel0 : (rank == 1 ? bel1 : bel2);
    int b = bel[lr];
    float v = g_xB[(size_t)grow * C + threadIdx.x];
    atomicAdd(&g_pooled[rank * NB * C + b * C + threadIdx.x], v);
}

__global__ void out_kernel(const float* __restrict__ Wr0, const float* __restrict__ br0,
                           const float* __restrict__ Wr1, const float* __restrict__ br1,
                           const float* __restrict__ Wr2, const float* __restrict__ br2,
                           float* __restrict__ out) {
    int b = blockIdx.x;
    int o = threadIdx.x;
    float acc = br0[o] + br1[o] + br2[o];
    const float* Wrs[3] = {Wr0, Wr1, Wr2};
    #pragma unroll
    for (int r = 0; r < 3; r++) {
        const float* Wr = Wrs[r];
        const float* p  = &g_pooled[r * NB * C + b * C];
        #pragma unroll 8
        for (int c = 0; c < C; c++) acc += p[c] * Wr[c * OUTC + o];
    }
    out[b * OUTC + o] = acc;
}

// ============================================================
extern "C" void kernel_launch(void* const* d_in, const int* in_sizes, int n_in,
                              void* d_out, int out_size) {
    const float* x0  = (const float*)d_in[0];
    const float* x1  = (const float*)d_in[1];
    const float* x2  = (const float*)d_in[2];
    const float* L0  = (const float*)d_in[3];
    const float* L1  = (const float*)d_in[4];
    const float* L2  = (const float*)d_in[5];
    const int*   bel0 = (const int*)d_in[6];
    const int*   bel1 = (const int*)d_in[7];
    const int*   bel2 = (const int*)d_in[8];
    const float* W0  = (const float*)d_in[9];
    const float* W1  = (const float*)d_in[10];
    const float* W2  = (const float*)d_in[11];
    const float* Wr0 = (const float*)d_in[12];
    const float* br0 = (const float*)d_in[13];
    const float* Wr1 = (const float*)d_in[14];
    const float* br1 = (const float*)d_in[15];
    const float* Wr2 = (const float*)d_in[16];
    const float* br2 = (const float*)d_in[17];

    cudaFuncSetAttribute(gemm_mma, cudaFuncAttributeMaxDynamicSharedMemorySize, GEMM_SMEM);

    dinv_kernel<<<NT, 128>>>(L0, L1, L2);

    for (int layer = 0; layer < 2; layer++) {
        xw_kernel<<<NT / 32, 256>>>(x0, x1, x2, W0, W1, W2, layer);
        gemm_mma<<<256, 256, GEMM_SMEM>>>(L0, L1, L2, layer);
    }

    zero_pooled_kernel<<<(3 * NB * C + 255) / 256, 256>>>();
    pool_kernel<<<NT, 64>>>(bel0, bel1, bel2);
    out_kernel<<<NB, OUTC>>>(Wr0, br0, Wr1, br1, Wr2, br2, (float*)d_out);
}

// round 9
// speedup vs baseline: 1.6421x; 1.5104x over previous
#include <cuda_runtime.h>
#include <cstdint>

#define NR0 4096
#define NR1 8192
#define NR2 4096
#define NT  16384     // NR0+NR1+NR2
#define C   64
#define OUTC 32
#define NB  64

// bf16 copies of the L matrices (written once by dinv_conv_kernel)
#define LBF_OFF0 0
#define LBF_OFF1 ((size_t)NR0 * NR0)                          // 16777216
#define LBF_OFF2 (LBF_OFF1 + (size_t)NR1 * NR1)               // 83886080
#define LBF_TOTAL (LBF_OFF2 + (size_t)NR2 * NR2)              // 100663296

// ---- scratch (device globals; no allocation allowed) ----
__device__ float    g_dinv[NT];
__device__ uint16_t g_Lbf[LBF_TOTAL];   // 192 MiB bf16 L
__device__ uint16_t g_zhi[C * NT];      // bf16 hi of z^T [C][NT]
__device__ uint16_t g_zlo[C * NT];      // bf16 lo
__device__ float    g_xA[NT * C];
__device__ float    g_xB[NT * C];
__device__ float    g_pooled[3 * NB * C];

// ============================================================
// helpers
// ============================================================
__device__ __forceinline__ uint32_t pack_bf16(float lo, float hi) {
    uint32_t r;
    asm("cvt.rn.bf16x2.f32 %0, %1, %2;" : "=r"(r) : "f"(hi), "f"(lo));
    return r;
}
__device__ __forceinline__ uint16_t bf16_rn(float x) {
    uint16_t r;
    asm("cvt.rn.bf16.f32 %0, %1;" : "=h"(r) : "f"(x));
    return r;
}
__device__ __forceinline__ void mma_bf16(float* c, const uint32_t* a, const uint32_t* b) {
    asm volatile("mma.sync.aligned.m16n8k16.row.col.f32.bf16.bf16.f32 "
        "{%0,%1,%2,%3}, {%4,%5,%6,%7}, {%8,%9}, {%0,%1,%2,%3};"
        : "+f"(c[0]), "+f"(c[1]), "+f"(c[2]), "+f"(c[3])
        : "r"(a[0]), "r"(a[1]), "r"(a[2]), "r"(a[3]), "r"(b[0]), "r"(b[1]));
}
__device__ __forceinline__ void ldsm_x4(uint32_t& r0, uint32_t& r1, uint32_t& r2,
                                        uint32_t& r3, uint32_t addr) {
    asm volatile("ldmatrix.sync.aligned.m8n8.x4.shared.b16 {%0,%1,%2,%3}, [%4];"
                 : "=r"(r0), "=r"(r1), "=r"(r2), "=r"(r3) : "r"(addr));
}
__device__ __forceinline__ void cp16(uint32_t smaddr, const void* g) {
    asm volatile("cp.async.cg.shared.global [%0], [%1], 16;" :: "r"(smaddr), "l"(g));
}
#define CP_COMMIT() asm volatile("cp.async.commit_group;" ::: "memory")
#define CP_WAIT1()  asm volatile("cp.async.wait_group 1;" ::: "memory")

// ============================================================
// fused: dinv[i] = rsqrt(rowsum |L_i|)  AND  g_Lbf = bf16(L)
// ============================================================
__global__ void dinv_conv_kernel(const float* __restrict__ L0,
                                 const float* __restrict__ L1,
                                 const float* __restrict__ L2) {
    int grow = blockIdx.x;
    const float* L; int N; int lr; size_t lbfOff;
    if (grow < NR0)             { L = L0; N = NR0; lr = grow;             lbfOff = LBF_OFF0; }
    else if (grow < NR0 + NR1)  { L = L1; N = NR1; lr = grow - NR0;       lbfOff = LBF_OFF1; }
    else                        { L = L2; N = NR2; lr = grow - NR0 - NR1; lbfOff = LBF_OFF2; }

    const float4* row = (const float4*)(L + (size_t)lr * N);
    uint2* rowOut = (uint2*)(g_Lbf + lbfOff + (size_t)lr * N);
    int n4 = N >> 2;
    float s = 0.f;
    for (int j = threadIdx.x; j < n4; j += blockDim.x) {
        float4 v = row[j];
        s += fabsf(v.x) + fabsf(v.y) + fabsf(v.z) + fabsf(v.w);
        rowOut[j] = make_uint2(pack_bf16(v.x, v.y), pack_bf16(v.z, v.w));
    }
    __shared__ float red[4];
    for (int o = 16; o > 0; o >>= 1) s += __shfl_down_sync(0xffffffffu, s, o);
    if ((threadIdx.x & 31) == 0) red[threadIdx.x >> 5] = s;
    __syncthreads();
    if (threadIdx.x == 0) {
        float d = red[0] + red[1] + red[2] + red[3];
        g_dinv[grow] = (d != 0.f) ? rsqrtf(d) : 0.f;
    }
}

// ============================================================
// z = dinv .* (x @ W[layer]); emit bf16 hi/lo transposed [C][NT]
// ============================================================
__global__ __launch_bounds__(256) void xw_kernel(
    const float* __restrict__ x0, const float* __restrict__ x1,
    const float* __restrict__ x2,
    const float* __restrict__ W0, const float* __restrict__ W1,
    const float* __restrict__ W2, int layer)
{
    __shared__ float Ws[C * C];
    __shared__ float xs[32 * C];
    __shared__ float zs[32][C + 1];

    int growBase = blockIdx.x * 32;
    const float* W; const float* xsrc;
    if (growBase < NR0) {
        W = W0;
        xsrc = layer ? (g_xA + (size_t)growBase * C) : (x0 + (size_t)growBase * C);
    } else if (growBase < NR0 + NR1) {
        W = W1;
        xsrc = layer ? (g_xA + (size_t)growBase * C) : (x1 + (size_t)(growBase - NR0) * C);
    } else {
        W = W2;
        xsrc = layer ? (g_xA + (size_t)growBase * C) : (x2 + (size_t)(growBase - NR0 - NR1) * C);
    }
    W += layer * C * C;

    int tid = threadIdx.x;
    for (int i = tid; i < C * C; i += 256) Ws[i] = W[i];
    for (int i = tid; i < 32 * C; i += 256) xs[i] = xsrc[i];
    __syncthreads();

    int c = tid & 63, rb = tid >> 6;
    #pragma unroll
    for (int rq = 0; rq < 8; rq++) {
        int r = rb * 8 + rq;
        float acc = 0.f;
        #pragma unroll
        for (int k = 0; k < C; k++) acc += xs[r * C + k] * Ws[k * C + c];
        zs[r][c] = acc * g_dinv[growBase + r];
    }
    __syncthreads();

    int c2 = tid >> 2, seg = tid & 3;
    size_t base = (size_t)c2 * NT + growBase + seg * 8;
    uint16_t hv[8], lv[8];
    #pragma unroll
    for (int j = 0; j < 8; j++) {
        float v = zs[seg * 8 + j][c2];
        uint16_t h = bf16_rn(v);
        hv[j] = h;
        lv[j] = bf16_rn(v - __uint_as_float((uint32_t)h << 16));
    }
    *(uint4*)&g_zhi[base] = *(uint4*)hv;
    *(uint4*)&g_zlo[base] = *(uint4*)lv;
}

// ============================================================
// cp.async bf16x2 GEMM:  dst = relu(dinv .* (L @ z))
//   D = Ah*Bh + Ah*Bl ;  A = g_Lbf (bf16, pre-converted)
// BM=64, BN=64, BK=64, 3-stage cp.async pipeline, 1 bar/chunk.
// 256 thr = 8 warps (2m x 4n), warp tile m32n16. 256 CTAs, rank1 first.
// ============================================================
#define SA 72   // smem row pitch in halves (64 data + 8 pad); 144B = 9*16
#define AH_OFF 0
#define BH_OFF (64 * SA)
#define BL_OFF (2 * 64 * SA)
#define STAGE_HALVES (3 * 64 * SA)           // 13824 halves = 27648 B
#define STAGE_BYTES  (STAGE_HALVES * 2)
#define NSTAGE 3
#define GEMM_SMEM (NSTAGE * STAGE_BYTES)     // 82944 B

__global__ __launch_bounds__(256, 2) void gemm_mma(int layer)
{
    extern __shared__ __align__(16) uint16_t sm[];

    // rank-1 CTAs first (longest jobs start in wave 1)
    int bx = blockIdx.x;
    int N, lrowBase, growBase; size_t lbfOff;
    if (bx < 128)      { N = NR1; lrowBase = bx * 64;         growBase = NR0 + lrowBase; lbfOff = LBF_OFF1; }
    else if (bx < 192) { N = NR0; lrowBase = (bx - 128) * 64; growBase = lrowBase;       lbfOff = LBF_OFF0; }
    else               { N = NR2; lrowBase = (bx - 192) * 64; growBase = NR0 + NR1 + lrowBase; lbfOff = LBF_OFF2; }
    int zOff = growBase - lrowBase;
    int nc = N / 64;
    float* dst = layer ? g_xB : g_xA;

    int tid = threadIdx.x;
    int wid = tid >> 5, lane = tid & 31;
    int g = lane >> 2, tg = lane & 3;
    int wm = wid >> 2, wn = wid & 3;     // 2m x 4n warp grid, tile m32n16

    uint32_t smBase = (uint32_t)__cvta_generic_to_shared(sm);

    // ---- ldmatrix lane byte offsets (within stage; add ks*32 bytes per k16 step) ----
    uint32_t aBase[2];
    #pragma unroll
    for (int mt = 0; mt < 2; mt++) {
        int row = wm * 32 + mt * 16 + (lane & 15);
        int col = (lane & 16) ? 8 : 0;
        aBase[mt] = 2u * (AH_OFF + row * SA + col);
    }
    uint32_t bhBase, blBase;
    {
        int row = wn * 16 + (lane & 7) + ((lane & 16) >> 1);
        int col = (lane & 8) ? 8 : 0;
        bhBase = 2u * (BH_OFF + row * SA + col);
        blBase = 2u * (BL_OFF + row * SA + col);
    }

    // ---- cp.async loader setup (per chunk: A 8KB, Bh 8KB, Bl 8KB; 6 x 16B/thread) ----
    const uint16_t* aSrc[2]; uint32_t aDst[2];
    #pragma unroll
    for (int q = 0; q < 2; q++) {
        int idx = q * 256 + tid;
        int aRow = idx >> 3, aSeg = idx & 7;
        aSrc[q] = g_Lbf + lbfOff + (size_t)(lrowBase + aRow) * N + aSeg * 8;
        aDst[q] = 2u * (AH_OFF + aRow * SA + aSeg * 8);
    }
    const uint16_t* bhSrc[2]; const uint16_t* blSrc[2]; uint32_t bhDst[2], blDst[2];
    #pragma unroll
    for (int q = 0; q < 2; q++) {
        int idx = q * 256 + tid;
        int bRow = idx >> 3, bSeg = idx & 7;
        bhSrc[q] = g_zhi + (size_t)bRow * NT + zOff + bSeg * 8;
        blSrc[q] = g_zlo + (size_t)bRow * NT + zOff + bSeg * 8;
        bhDst[q] = 2u * (BH_OFF + bRow * SA + bSeg * 8);
        blDst[q] = 2u * (BL_OFF + bRow * SA + bSeg * 8);
    }

    float acc[2][2][4];
    #pragma unroll
    for (int mt = 0; mt < 2; mt++)
        #pragma unroll
        for (int nt = 0; nt < 2; nt++)
            #pragma unroll
            for (int i = 0; i < 4; i++) acc[mt][nt][i] = 0.f;

    // stage index tracker (avoid % in loop)
    int sIssue = 0;   // stage for next issued chunk
    int sComp = 0;    // stage for next computed chunk

    // ---- prologue: issue chunks 0,1 ----
    #pragma unroll
    for (int p = 0; p < 2; p++) {
        uint32_t st = smBase + (uint32_t)sIssue * STAGE_BYTES;
        int k0 = p * 64;
        #pragma unroll
        for (int q = 0; q < 2; q++) cp16(st + aDst[q], aSrc[q] + k0);
        #pragma unroll
        for (int q = 0; q < 2; q++) cp16(st + bhDst[q], bhSrc[q] + k0);
        #pragma unroll
        for (int q = 0; q < 2; q++) cp16(st + blDst[q], blSrc[q] + k0);
        CP_COMMIT();
        if (++sIssue == NSTAGE) sIssue = 0;
    }

    // ---- mainloop ----
    for (int cI = 0; cI < nc; cI++) {
        CP_WAIT1();
        __syncthreads();

        // issue chunk cI+2 into the stage computed last iteration
        if (cI + 2 < nc) {
            uint32_t st = smBase + (uint32_t)sIssue * STAGE_BYTES;
            int k0 = (cI + 2) * 64;
            #pragma unroll
            for (int q = 0; q < 2; q++) cp16(st + aDst[q], aSrc[q] + k0);
            #pragma unroll
            for (int q = 0; q < 2; q++) cp16(st + bhDst[q], bhSrc[q] + k0);
            #pragma unroll
            for (int q = 0; q < 2; q++) cp16(st + blDst[q], blSrc[q] + k0);
        }
        CP_COMMIT();   // unconditional: keeps wait_group accounting correct at tail
        if (++sIssue == NSTAGE) sIssue = 0;

        // compute current chunk
        uint32_t stage = smBase + (uint32_t)sComp * STAGE_BYTES;
        if (++sComp == NSTAGE) sComp = 0;
        #pragma unroll
        for (int ks = 0; ks < 4; ks++) {
            uint32_t ah[2][4];
            #pragma unroll
            for (int mt = 0; mt < 2; mt++)
                ldsm_x4(ah[mt][0], ah[mt][1], ah[mt][2], ah[mt][3],
                        stage + aBase[mt] + ks * 32);
            uint32_t bh[2][2], bl[2][2];
            ldsm_x4(bh[0][0], bh[0][1], bh[1][0], bh[1][1], stage + bhBase + ks * 32);
            ldsm_x4(bl[0][0], bl[0][1], bl[1][0], bl[1][1], stage + blBase + ks * 32);
            #pragma unroll
            for (int mt = 0; mt < 2; mt++)
                #pragma unroll
                for (int nt = 0; nt < 2; nt++) {
                    mma_bf16(acc[mt][nt], ah[mt], bh[nt]);
                    mma_bf16(acc[mt][nt], ah[mt], bl[nt]);
                }
        }
    }

    // ---- epilogue: dinv row-scale + relu, write fp32 ----
    #pragma unroll
    for (int mt = 0; mt < 2; mt++) {
        int row0 = wm * 32 + mt * 16 + g;
        float dv0 = g_dinv[growBase + row0];
        float dv1 = g_dinv[growBase + row0 + 8];
        #pragma unroll
        for (int nt = 0; nt < 2; nt++) {
            int col = wn * 16 + nt * 8 + tg * 2;
            float* c = acc[mt][nt];
            float2 o0, o1;
            o0.x = fmaxf(c[0] * dv0, 0.f);
            o0.y = fmaxf(c[1] * dv0, 0.f);
            o1.x = fmaxf(c[2] * dv1, 0.f);
            o1.y = fmaxf(c[3] * dv1, 0.f);
            *(float2*)&dst[(size_t)(growBase + row0) * C + col]     = o0;
            *(float2*)&dst[(size_t)(growBase + row0 + 8) * C + col] = o1;
        }
    }
}

// ============================================================
// readout
// ============================================================
__global__ void zero_pooled_kernel() {
    int i = blockIdx.x * blockDim.x + threadIdx.x;
    if (i < 3 * NB * C) g_pooled[i] = 0.f;
}

__global__ void pool_kernel(const int* __restrict__ bel0,
                            const int* __restrict__ bel1,
                            const int* __restrict__ bel2) {
    int grow = blockIdx.x;
    int rank, lr;
    if (grow < NR0)            { rank = 0; lr = grow; }
    else if (grow < NR0 + NR1) { rank = 1; lr = grow - NR0; }
    else                       { rank = 2; lr = grow - NR0 - NR1; }
    const int* bel = (rank == 0) ? bel0 : (rank == 1 ? bel1 : bel2);
    int b = bel[lr];
    float v = g_xB[(size_t)grow * C + threadIdx.x];
    atomicAdd(&g_pooled[rank * NB * C + b * C + threadIdx.x], v);
}

__global__ void out_kernel(const float* __restrict__ Wr0, const float* __restrict__ br0,
                           const float* __restrict__ Wr1, const float* __restrict__ br1,
                           const float* __restrict__ Wr2, const float* __restrict__ br2,
                           float* __restrict__ out) {
    int b = blockIdx.x;
    int o = threadIdx.x;
    float acc = br0[o] + br1[o] + br2[o];
    const float* Wrs[3] = {Wr0, Wr1, Wr2};
    #pragma unroll
    for (int r = 0; r < 3; r++) {
        const float* Wr = Wrs[r];
        const float* p  = &g_pooled[r * NB * C + b * C];
        #pragma unroll 8
        for (int c = 0; c < C; c++) acc += p[c] * Wr[c * OUTC + o];
    }
    out[b * OUTC + o] = acc;
}

// ============================================================
extern "C" void kernel_launch(void* const* d_in, const int* in_sizes, int n_in,
                              void* d_out, int out_size) {
    const float* x0  = (const float*)d_in[0];
    const float* x1  = (const float*)d_in[1];
    const float* x2  = (const float*)d_in[2];
    const float* L0  = (const float*)d_in[3];
    const float* L1  = (const float*)d_in[4];
    const float* L2  = (const float*)d_in[5];
    const int*   bel0 = (const int*)d_in[6];
    const int*   bel1 = (const int*)d_in[7];
    const int*   bel2 = (const int*)d_in[8];
    const float* W0  = (const float*)d_in[9];
    const float* W1  = (const float*)d_in[10];
    const float* W2  = (const float*)d_in[11];
    const float* Wr0 = (const float*)d_in[12];
    const float* br0 = (const float*)d_in[13];
    const float* Wr1 = (const float*)d_in[14];
    const float* br1 = (const float*)d_in[15];
    const float* Wr2 = (const float*)d_in[16];
    const float* br2 = (const float*)d_in[17];

    cudaFuncSetAttribute(gemm_mma, cudaFuncAttributeMaxDynamicSharedMemorySize, GEMM_SMEM);

    dinv_conv_kernel<<<NT, 128>>>(L0, L1, L2);

    for (int layer = 0; layer < 2; layer++) {
        xw_kernel<<<NT / 32, 256>>>(x0, x1, x2, W0, W1, W2, layer);
        gemm_mma<<<256, 256, GEMM_SMEM>>>(layer);
    }

    zero_pooled_kernel<<<(3 * NB * C + 255) / 256, 256>>>();
    pool_kernel<<<NT, 64>>>(bel0, bel1, bel2);
    out_kernel<<<NB, OUTC>>>(Wr0, br0, Wr1, br1, Wr2, br2, (float*)d_out);
}

// round 10
// speedup vs baseline: 1.9562x; 1.1913x over previous
#include <cuda_runtime.h>
#include <cuda_fp16.h>
#include <cstdint>

#define NR0 4096
#define NR1 8192
#define NR2 4096
#define NT  16384     // NR0+NR1+NR2
#define C   64
#define OUTC 32
#define NB  64

// fp16 copies of the L matrices (written once by dinv_conv_kernel)
#define LBF_OFF0 0
#define LBF_OFF1 ((size_t)NR0 * NR0)
#define LBF_OFF2 (LBF_OFF1 + (size_t)NR1 * NR1)
#define LBF_TOTAL (LBF_OFF2 + (size_t)NR2 * NR2)

// ---- scratch (device globals; no allocation allowed) ----
__device__ float    g_dinv[NT];
__device__ uint16_t g_Lh[LBF_TOTAL];    // fp16 L
__device__ uint16_t g_zh[C * NT];       // fp16 z^T [C][NT] (K-major B operand)
__device__ float    g_xA[NT * C];
__device__ float    g_xB[NT * C];
__device__ float    g_pooled[3 * NB * C];

// ============================================================
// helpers
// ============================================================
__device__ __forceinline__ uint32_t pack_f16(float lo, float hi) {
    __half2 h = __floats2half2_rn(lo, hi);   // lo -> low 16 bits
    return *(uint32_t*)&h;
}
__device__ __forceinline__ void mma_f16(float* c, const uint32_t* a, const uint32_t* b) {
    asm volatile("mma.sync.aligned.m16n8k16.row.col.f32.f16.f16.f32 "
        "{%0,%1,%2,%3}, {%4,%5,%6,%7}, {%8,%9}, {%0,%1,%2,%3};"
        : "+f"(c[0]), "+f"(c[1]), "+f"(c[2]), "+f"(c[3])
        : "r"(a[0]), "r"(a[1]), "r"(a[2]), "r"(a[3]), "r"(b[0]), "r"(b[1]));
}
__device__ __forceinline__ void ldsm_x4(uint32_t& r0, uint32_t& r1, uint32_t& r2,
                                        uint32_t& r3, uint32_t addr) {
    asm volatile("ldmatrix.sync.aligned.m8n8.x4.shared.b16 {%0,%1,%2,%3}, [%4];"
                 : "=r"(r0), "=r"(r1), "=r"(r2), "=r"(r3) : "r"(addr));
}
__device__ __forceinline__ void cp16(uint32_t smaddr, const void* g) {
    asm volatile("cp.async.cg.shared.global [%0], [%1], 16;" :: "r"(smaddr), "l"(g));
}
#define CP_COMMIT() asm volatile("cp.async.commit_group;" ::: "memory")
#define CP_WAIT2()  asm volatile("cp.async.wait_group 2;" ::: "memory")

// ============================================================
// fused: dinv[i] = rsqrt(rowsum |L_i|)  AND  g_Lh = fp16(L)
// ============================================================
__global__ void dinv_conv_kernel(const float* __restrict__ L0,
                                 const float* __restrict__ L1,
                                 const float* __restrict__ L2) {
    int grow = blockIdx.x;
    const float* L; int N; int lr; size_t lbfOff;
    if (grow < NR0)             { L = L0; N = NR0; lr = grow;             lbfOff = LBF_OFF0; }
    else if (grow < NR0 + NR1)  { L = L1; N = NR1; lr = grow - NR0;       lbfOff = LBF_OFF1; }
    else                        { L = L2; N = NR2; lr = grow - NR0 - NR1; lbfOff = LBF_OFF2; }

    const float4* row = (const float4*)(L + (size_t)lr * N);
    uint2* rowOut = (uint2*)(g_Lh + lbfOff + (size_t)lr * N);
    int n4 = N >> 2;
    float s = 0.f;
    for (int j = threadIdx.x; j < n4; j += blockDim.x) {
        float4 v = row[j];
        s += fabsf(v.x) + fabsf(v.y) + fabsf(v.z) + fabsf(v.w);
        rowOut[j] = make_uint2(pack_f16(v.x, v.y), pack_f16(v.z, v.w));
    }
    __shared__ float red[4];
    for (int o = 16; o > 0; o >>= 1) s += __shfl_down_sync(0xffffffffu, s, o);
    if ((threadIdx.x & 31) == 0) red[threadIdx.x >> 5] = s;
    __syncthreads();
    if (threadIdx.x == 0) {
        float d = red[0] + red[1] + red[2] + red[3];
        g_dinv[grow] = (d != 0.f) ? rsqrtf(d) : 0.f;
    }
}

// ============================================================
// z = dinv .* (x @ W[layer]); emit fp16 transposed [C][NT]
// ============================================================
__global__ __launch_bounds__(256) void xw_kernel(
    const float* __restrict__ x0, const float* __restrict__ x1,
    const float* __restrict__ x2,
    const float* __restrict__ W0, const float* __restrict__ W1,
    const float* __restrict__ W2, int layer)
{
    __shared__ float Ws[C * C];
    __shared__ float xs[32 * C];
    __shared__ float zs[32][C + 1];

    int growBase = blockIdx.x * 32;
    const float* W; const float* xsrc;
    if (growBase < NR0) {
        W = W0;
        xsrc = layer ? (g_xA + (size_t)growBase * C) : (x0 + (size_t)growBase * C);
    } else if (growBase < NR0 + NR1) {
        W = W1;
        xsrc = layer ? (g_xA + (size_t)growBase * C) : (x1 + (size_t)(growBase - NR0) * C);
    } else {
        W = W2;
        xsrc = layer ? (g_xA + (size_t)growBase * C) : (x2 + (size_t)(growBase - NR0 - NR1) * C);
    }
    W += layer * C * C;

    int tid = threadIdx.x;
    for (int i = tid; i < C * C; i += 256) Ws[i] = W[i];
    for (int i = tid; i < 32 * C; i += 256) xs[i] = xsrc[i];
    __syncthreads();

    int c = tid & 63, rb = tid >> 6;
    #pragma unroll
    for (int rq = 0; rq < 8; rq++) {
        int r = rb * 8 + rq;
        float acc = 0.f;
        #pragma unroll
        for (int k = 0; k < C; k++) acc += xs[r * C + k] * Ws[k * C + c];
        zs[r][c] = acc * g_dinv[growBase + r];
    }
    __syncthreads();

    int c2 = tid >> 2, seg = tid & 3;
    size_t base = (size_t)c2 * NT + growBase + seg * 8;
    uint16_t hv[8];
    #pragma unroll
    for (int j = 0; j < 8; j++)
        hv[j] = __half_as_ushort(__float2half_rn(zs[seg * 8 + j][c2]));
    *(uint4*)&g_zh[base] = *(uint4*)hv;
}

// ============================================================
// cp.async fp16 GEMM:  dst = relu(dinv .* (L @ z)),  D = A*B (single MMA)
// BM=64, BN=64, BK=64, 4-stage cp.async pipeline, 1 bar/chunk.
// 256 thr = 8 warps (2m x 4n), warp tile m32n16. 256 CTAs, rank1 first.
// ============================================================
#define SA 72   // smem row pitch in halves (64 data + 8 pad); 144B
#define AH_OFF 0
#define BH_OFF (64 * SA)
#define STAGE_HALVES (2 * 64 * SA)           // 9216 halves = 18432 B
#define STAGE_BYTES  (STAGE_HALVES * 2)
#define NSTAGE 4
#define GEMM_SMEM (NSTAGE * STAGE_BYTES)     // 73728 B

__global__ __launch_bounds__(256, 2) void gemm_mma(int layer)
{
    extern __shared__ __align__(16) uint16_t sm[];

    // rank-1 CTAs first (longest jobs start in wave 1)
    int bx = blockIdx.x;
    int N, lrowBase, growBase; size_t lbfOff;
    if (bx < 128)      { N = NR1; lrowBase = bx * 64;         growBase = NR0 + lrowBase; lbfOff = LBF_OFF1; }
    else if (bx < 192) { N = NR0; lrowBase = (bx - 128) * 64; growBase = lrowBase;       lbfOff = LBF_OFF0; }
    else               { N = NR2; lrowBase = (bx - 192) * 64; growBase = NR0 + NR1 + lrowBase; lbfOff = LBF_OFF2; }
    int zOff = growBase - lrowBase;
    int nc = N / 64;
    float* dst = layer ? g_xB : g_xA;

    int tid = threadIdx.x;
    int wid = tid >> 5, lane = tid & 31;
    int g = lane >> 2, tg = lane & 3;
    int wm = wid >> 2, wn = wid & 3;     // 2m x 4n warp grid, tile m32n16

    uint32_t smBase = (uint32_t)__cvta_generic_to_shared(sm);

    // ---- ldmatrix lane byte offsets (within stage; +ks*32 bytes per k16 step) ----
    uint32_t aBase[2];
    #pragma unroll
    for (int mt = 0; mt < 2; mt++) {
        int row = wm * 32 + mt * 16 + (lane & 15);
        int col = (lane & 16) ? 8 : 0;
        aBase[mt] = 2u * (AH_OFF + row * SA + col);
    }
    uint32_t bBase;
    {
        int row = wn * 16 + (lane & 7) + ((lane & 16) >> 1);
        int col = (lane & 8) ? 8 : 0;
        bBase = 2u * (BH_OFF + row * SA + col);
    }

    // ---- cp.async loader setup (per chunk: A 8KB + B 8KB; 4 x 16B/thread) ----
    const uint16_t* aSrc[2]; uint32_t aDst[2];
    #pragma unroll
    for (int q = 0; q < 2; q++) {
        int idx = q * 256 + tid;
        int aRow = idx >> 3, aSeg = idx & 7;
        aSrc[q] = g_Lh + lbfOff + (size_t)(lrowBase + aRow) * N + aSeg * 8;
        aDst[q] = 2u * (AH_OFF + aRow * SA + aSeg * 8);
    }
    const uint16_t* bSrc[2]; uint32_t bDst[2];
    #pragma unroll
    for (int q = 0; q < 2; q++) {
        int idx = q * 256 + tid;
        int bRow = idx >> 3, bSeg = idx & 7;
        bSrc[q] = g_zh + (size_t)bRow * NT + zOff + bSeg * 8;
        bDst[q] = 2u * (BH_OFF + bRow * SA + bSeg * 8);
    }

    float acc[2][2][4];
    #pragma unroll
    for (int mt = 0; mt < 2; mt++)
        #pragma unroll
        for (int nt = 0; nt < 2; nt++)
            #pragma unroll
            for (int i = 0; i < 4; i++) acc[mt][nt][i] = 0.f;

    int sIssue = 0, sComp = 0;

    // ---- prologue: issue chunks 0,1,2 ----
    #pragma unroll
    for (int p = 0; p < 3; p++) {
        uint32_t st = smBase + (uint32_t)sIssue * STAGE_BYTES;
        int k0 = p * 64;
        #pragma unroll
        for (int q = 0; q < 2; q++) cp16(st + aDst[q], aSrc[q] + k0);
        #pragma unroll
        for (int q = 0; q < 2; q++) cp16(st + bDst[q], bSrc[q] + k0);
        CP_COMMIT();
        if (++sIssue == NSTAGE) sIssue = 0;
    }

    // ---- mainloop ----
    for (int cI = 0; cI < nc; cI++) {
        CP_WAIT2();
        __syncthreads();

        // issue chunk cI+3 (stage freed by chunk cI-1's compute last iteration)
        if (cI + 3 < nc) {
            uint32_t st = smBase + (uint32_t)sIssue * STAGE_BYTES;
            int k0 = (cI + 3) * 64;
            #pragma unroll
            for (int q = 0; q < 2; q++) cp16(st + aDst[q], aSrc[q] + k0);
            #pragma unroll
            for (int q = 0; q < 2; q++) cp16(st + bDst[q], bSrc[q] + k0);
        }
        CP_COMMIT();   // unconditional: keeps wait_group accounting correct at tail
        if (++sIssue == NSTAGE) sIssue = 0;

        // compute current chunk
        uint32_t stage = smBase + (uint32_t)sComp * STAGE_BYTES;
        if (++sComp == NSTAGE) sComp = 0;
        #pragma unroll
        for (int ks = 0; ks < 4; ks++) {
            uint32_t ah[2][4];
            #pragma unroll
            for (int mt = 0; mt < 2; mt++)
                ldsm_x4(ah[mt][0], ah[mt][1], ah[mt][2], ah[mt][3],
                        stage + aBase[mt] + ks * 32);
            uint32_t bv[2][2];
            ldsm_x4(bv[0][0], bv[0][1], bv[1][0], bv[1][1], stage + bBase + ks * 32);
            #pragma unroll
            for (int mt = 0; mt < 2; mt++)
                #pragma unroll
                for (int nt = 0; nt < 2; nt++)
                    mma_f16(acc[mt][nt], ah[mt], bv[nt]);
        }
    }

    // ---- epilogue: dinv row-scale + relu, write fp32 ----
    #pragma unroll
    for (int mt = 0; mt < 2; mt++) {
        int row0 = wm * 32 + mt * 16 + g;
        float dv0 = g_dinv[growBase + row0];
        float dv1 = g_dinv[growBase + row0 + 8];
        #pragma unroll
        for (int nt = 0; nt < 2; nt++) {
            int col = wn * 16 + nt * 8 + tg * 2;
            float* c = acc[mt][nt];
            float2 o0, o1;
            o0.x = fmaxf(c[0] * dv0, 0.f);
            o0.y = fmaxf(c[1] * dv0, 0.f);
            o1.x = fmaxf(c[2] * dv1, 0.f);
            o1.y = fmaxf(c[3] * dv1, 0.f);
            *(float2*)&dst[(size_t)(growBase + row0) * C + col]     = o0;
            *(float2*)&dst[(size_t)(growBase + row0 + 8) * C + col] = o1;
        }
    }
}

// ============================================================
// readout
// ============================================================
__global__ void zero_pooled_kernel() {
    int i = blockIdx.x * blockDim.x + threadIdx.x;
    if (i < 3 * NB * C) g_pooled[i] = 0.f;
}

__global__ void pool_kernel(const int* __restrict__ bel0,
                            const int* __restrict__ bel1,
                            const int* __restrict__ bel2) {
    int grow = blockIdx.x;
    int rank, lr;
    if (grow < NR0)            { rank = 0; lr = grow; }
    else if (grow < NR0 + NR1) { rank = 1; lr = grow - NR0; }
    else                       { rank = 2; lr = grow - NR0 - NR1; }
    const int* bel = (rank == 0) ? bel0 : (rank == 1 ? bel1 : bel2);
    int b = bel[lr];
    float v = g_xB[(size_t)grow * C + threadIdx.x];
    atomicAdd(&g_pooled[rank * NB * C + b * C + threadIdx.x], v);
}

__global__ void out_kernel(const float* __restrict__ Wr0, const float* __restrict__ br0,
                           const float* __restrict__ Wr1, const float* __restrict__ br1,
                           const float* __restrict__ Wr2, const float* __restrict__ br2,
                           float* __restrict__ out) {
    int b = blockIdx.x;
    int o = threadIdx.x;
    float acc = br0[o] + br1[o] + br2[o];
    const float* Wrs[3] = {Wr0, Wr1, Wr2};
    #pragma unroll
    for (int r = 0; r < 3; r++) {
        const float* Wr = Wrs[r];
        const float* p  = &g_pooled[r * NB * C + b * C];
        #pragma unroll 8
        for (int c = 0; c < C; c++) acc += p[c] * Wr[c * OUTC + o];
    }
    out[b * OUTC + o] = acc;
}

// ============================================================
extern "C" void kernel_launch(void* const* d_in, const int* in_sizes, int n_in,
                              void* d_out, int out_size) {
    const float* x0  = (const float*)d_in[0];
    const float* x1  = (const float*)d_in[1];
    const float* x2  = (const float*)d_in[2];
    const float* L0  = (const float*)d_in[3];
    const float* L1  = (const float*)d_in[4];
    const float* L2  = (const float*)d_in[5];
    const int*   bel0 = (const int*)d_in[6];
    const int*   bel1 = (const int*)d_in[7];
    const int*   bel2 = (const int*)d_in[8];
    const float* W0  = (const float*)d_in[9];
    const float* W1  = (const float*)d_in[10];
    const float* W2  = (const float*)d_in[11];
    const float* Wr0 = (const float*)d_in[12];
    const float* br0 = (const float*)d_in[13];
    const float* Wr1 = (const float*)d_in[14];
    const float* br1 = (const float*)d_in[15];
    const float* Wr2 = (const float*)d_in[16];
    const float* br2 = (const float*)d_in[17];

    cudaFuncSetAttribute(gemm_mma, cudaFuncAttributeMaxDynamicSharedMemorySize, GEMM_SMEM);

    dinv_conv_kernel<<<NT, 128>>>(L0, L1, L2);

    for (int layer = 0; layer < 2; layer++) {
        xw_kernel<<<NT / 32, 256>>>(x0, x1, x2, W0, W1, W2, layer);
        gemm_mma<<<256, 256, GEMM_SMEM>>>(layer);
    }

    zero_pooled_kernel<<<(3 * NB * C + 255) / 256, 256>>>();
    pool_kernel<<<NT, 64>>>(bel0, bel1, bel2);
    out_kernel<<<NB, OUTC>>>(Wr0, br0, Wr1, br1, Wr2, br2, (float*)d_out);
}

// round 11
// speedup vs baseline: 2.1013x; 1.0742x over previous
#include <cuda_runtime.h>
#include <cuda_fp16.h>
#include <cstdint>

#define NR0 4096
#define NR1 8192
#define NR2 4096
#define NT  16384     // NR0+NR1+NR2
#define C   64
#define OUTC 32
#define NB  64

// fp16 copies of the L matrices (written once by dinv_conv_kernel)
#define LBF_OFF0 0
#define LBF_OFF1 ((size_t)NR0 * NR0)
#define LBF_OFF2 (LBF_OFF1 + (size_t)NR1 * NR1)
#define LBF_TOTAL (LBF_OFF2 + (size_t)NR2 * NR2)

// ---- scratch (device globals; no allocation allowed) ----
__device__ float    g_dinv[NT];
__device__ uint16_t g_Lh[LBF_TOTAL];    // fp16 L
__device__ uint16_t g_zh[C * NT];       // fp16 z^T [C][NT] (K-major B operand)
__device__ float    g_xA[NT * C];
__device__ float    g_xB[NT * C];
__device__ float    g_pooled[3 * NB * C];

// ============================================================
// helpers
// ============================================================
__device__ __forceinline__ uint32_t pack_f16(float lo, float hi) {
    __half2 h = __floats2half2_rn(lo, hi);   // lo -> low 16 bits
    return *(uint32_t*)&h;
}
__device__ __forceinline__ void mma_f16(float* c, const uint32_t* a, const uint32_t* b) {
    asm volatile("mma.sync.aligned.m16n8k16.row.col.f32.f16.f16.f32 "
        "{%0,%1,%2,%3}, {%4,%5,%6,%7}, {%8,%9}, {%0,%1,%2,%3};"
        : "+f"(c[0]), "+f"(c[1]), "+f"(c[2]), "+f"(c[3])
        : "r"(a[0]), "r"(a[1]), "r"(a[2]), "r"(a[3]), "r"(b[0]), "r"(b[1]));
}
__device__ __forceinline__ void ldsm_x4(uint32_t& r0, uint32_t& r1, uint32_t& r2,
                                        uint32_t& r3, uint32_t addr) {
    asm volatile("ldmatrix.sync.aligned.m8n8.x4.shared.b16 {%0,%1,%2,%3}, [%4];"
                 : "=r"(r0), "=r"(r1), "=r"(r2), "=r"(r3) : "r"(addr));
}
__device__ __forceinline__ void cp16(uint32_t smaddr, const void* g) {
    asm volatile("cp.async.cg.shared.global [%0], [%1], 16;" :: "r"(smaddr), "l"(g));
}
#define CP_COMMIT() asm volatile("cp.async.commit_group;" ::: "memory")
#define CP_WAIT2()  asm volatile("cp.async.wait_group 2;" ::: "memory")

// ============================================================
// fused: dinv[i] = rsqrt(rowsum |L_i|)  AND  g_Lh = fp16(L)
// ============================================================
__global__ void dinv_conv_kernel(const float* __restrict__ L0,
                                 const float* __restrict__ L1,
                                 const float* __restrict__ L2) {
    int grow = blockIdx.x;
    const float* L; int N; int lr; size_t lbfOff;
    if (grow < NR0)             { L = L0; N = NR0; lr = grow;             lbfOff = LBF_OFF0; }
    else if (grow < NR0 + NR1)  { L = L1; N = NR1; lr = grow - NR0;       lbfOff = LBF_OFF1; }
    else                        { L = L2; N = NR2; lr = grow - NR0 - NR1; lbfOff = LBF_OFF2; }

    const float4* row = (const float4*)(L + (size_t)lr * N);
    uint2* rowOut = (uint2*)(g_Lh + lbfOff + (size_t)lr * N);
    int n4 = N >> 2;
    float s = 0.f;
    for (int j = threadIdx.x; j < n4; j += blockDim.x) {
        float4 v = row[j];
        s += fabsf(v.x) + fabsf(v.y) + fabsf(v.z) + fabsf(v.w);
        rowOut[j] = make_uint2(pack_f16(v.x, v.y), pack_f16(v.z, v.w));
    }
    __shared__ float red[4];
    for (int o = 16; o > 0; o >>= 1) s += __shfl_down_sync(0xffffffffu, s, o);
    if ((threadIdx.x & 31) == 0) red[threadIdx.x >> 5] = s;
    __syncthreads();
    if (threadIdx.x == 0) {
        float d = red[0] + red[1] + red[2] + red[3];
        g_dinv[grow] = (d != 0.f) ? rsqrtf(d) : 0.f;
    }
}

// ============================================================
// z = dinv .* (x @ W[layer]); emit fp16 transposed [C][NT]
// 4x4 register-tiled: 64 rows/block, 256 thr, 2B smem traffic/FMA.
// ============================================================
#define XSP 68   // xs row pitch in floats (16B-aligned, conflict-free)
#define ZSP 72   // zs row pitch in halves

__global__ __launch_bounds__(256) void xw_kernel(
    const float* __restrict__ x0, const float* __restrict__ x1,
    const float* __restrict__ x2,
    const float* __restrict__ W0, const float* __restrict__ W1,
    const float* __restrict__ W2, int layer)
{
    __shared__ __align__(16) char sbuf[16384 + 64 * XSP * 4];   // 33792 B
    float* Ws = (float*)sbuf;                   // [64][64]
    float* xs = (float*)(sbuf + 16384);         // [64][XSP]

    int growBase = blockIdx.x * 64;
    const float* W; const float* xsrc;
    if (growBase < NR0) {
        W = W0;
        xsrc = layer ? (g_xA + (size_t)growBase * C) : (x0 + (size_t)growBase * C);
    } else if (growBase < NR0 + NR1) {
        W = W1;
        xsrc = layer ? (g_xA + (size_t)growBase * C) : (x1 + (size_t)(growBase - NR0) * C);
    } else {
        W = W2;
        xsrc = layer ? (g_xA + (size_t)growBase * C) : (x2 + (size_t)(growBase - NR0 - NR1) * C);
    }
    W += layer * C * C;

    int tid = threadIdx.x;
    for (int i = tid; i < C * C; i += 256) Ws[i] = W[i];
    // xs: 64 rows x 16 float4 = 1024 float4, 4 per thread
    for (int i = tid; i < 64 * 16; i += 256) {
        int row = i >> 4, q = i & 15;
        *(float4*)&xs[row * XSP + q * 4] = *(const float4*)(xsrc + row * C + q * 4);
    }
    __syncthreads();

    int tx = tid & 15, ty = tid >> 4;           // 16x16 thread grid; 4x4 tile each
    const float4* Ws4 = (const float4*)Ws;

    float acc[4][4];
    #pragma unroll
    for (int i = 0; i < 4; i++)
        #pragma unroll
        for (int j = 0; j < 4; j++) acc[i][j] = 0.f;

    #pragma unroll 8
    for (int k = 0; k < C; k++) {
        float4 w = Ws4[k * 16 + tx];
        #pragma unroll
        for (int i = 0; i < 4; i++) {
            float a = xs[(ty * 4 + i) * XSP + k];
            acc[i][0] += a * w.x;
            acc[i][1] += a * w.y;
            acc[i][2] += a * w.z;
            acc[i][3] += a * w.w;
        }
    }
    __syncthreads();   // xs/Ws reads done; sbuf may be overwritten

    // scale by dinv, convert fp16, stage into overlaid zs
    uint16_t* zs = (uint16_t*)sbuf;             // [64][ZSP] halves = 9216 B
    #pragma unroll
    for (int i = 0; i < 4; i++) {
        int row = ty * 4 + i;
        float dv = g_dinv[growBase + row];
        uint2 p;
        p.x = pack_f16(acc[i][0] * dv, acc[i][1] * dv);
        p.y = pack_f16(acc[i][2] * dv, acc[i][3] * dv);
        *(uint2*)&zs[row * ZSP + tx * 4] = p;
    }
    __syncthreads();

    // transposed write: thread -> channel c2, 16 consecutive rows (2 x uint4)
    int c2 = tid >> 2, seg = tid & 3;
    size_t base = (size_t)c2 * NT + growBase + seg * 16;
    uint16_t hv[16];
    #pragma unroll
    for (int j = 0; j < 16; j++) hv[j] = zs[(seg * 16 + j) * ZSP + c2];
    *(uint4*)&g_zh[base]     = *(uint4*)hv;
    *(uint4*)&g_zh[base + 8] = *(uint4*)(hv + 8);
}

// ============================================================
// cp.async fp16 GEMM:  dst = relu(dinv .* (L @ z)),  D = A*B (single MMA)
// BM=64, BN=64, BK=64, 4-stage cp.async pipeline, 1 bar/chunk.
// 256 thr = 8 warps (2m x 4n), warp tile m32n16. 256 CTAs, rank1 first.
// ============================================================
#define SA 72   // smem row pitch in halves (64 data + 8 pad); 144B
#define AH_OFF 0
#define BH_OFF (64 * SA)
#define STAGE_HALVES (2 * 64 * SA)           // 9216 halves = 18432 B
#define STAGE_BYTES  (STAGE_HALVES * 2)
#define NSTAGE 4
#define GEMM_SMEM (NSTAGE * STAGE_BYTES)     // 73728 B

__global__ __launch_bounds__(256, 2) void gemm_mma(int layer)
{
    extern __shared__ __align__(16) uint16_t sm[];

    // rank-1 CTAs first (longest jobs start in wave 1)
    int bx = blockIdx.x;
    int N, lrowBase, growBase; size_t lbfOff;
    if (bx < 128)      { N = NR1; lrowBase = bx * 64;         growBase = NR0 + lrowBase; lbfOff = LBF_OFF1; }
    else if (bx < 192) { N = NR0; lrowBase = (bx - 128) * 64; growBase = lrowBase;       lbfOff = LBF_OFF0; }
    else               { N = NR2; lrowBase = (bx - 192) * 64; growBase = NR0 + NR1 + lrowBase; lbfOff = LBF_OFF2; }
    int zOff = growBase - lrowBase;
    int nc = N / 64;
    float* dst = layer ? g_xB : g_xA;

    int tid = threadIdx.x;
    int wid = tid >> 5, lane = tid & 31;
    int g = lane >> 2, tg = lane & 3;
    int wm = wid >> 2, wn = wid & 3;     // 2m x 4n warp grid, tile m32n16

    uint32_t smBase = (uint32_t)__cvta_generic_to_shared(sm);

    // ---- ldmatrix lane byte offsets (within stage; +ks*32 bytes per k16 step) ----
    uint32_t aBase[2];
    #pragma unroll
    for (int mt = 0; mt < 2; mt++) {
        int row = wm * 32 + mt * 16 + (lane & 15);
        int col = (lane & 16) ? 8 : 0;
        aBase[mt] = 2u * (AH_OFF + row * SA + col);
    }
    uint32_t bBase;
    {
        int row = wn * 16 + (lane & 7) + ((lane & 16) >> 1);
        int col = (lane & 8) ? 8 : 0;
        bBase = 2u * (BH_OFF + row * SA + col);
    }

    // ---- cp.async loader setup (per chunk: A 8KB + B 8KB; 4 x 16B/thread) ----
    const uint16_t* aSrc[2]; uint32_t aDst[2];
    #pragma unroll
    for (int q = 0; q < 2; q++) {
        int idx = q * 256 + tid;
        int aRow = idx >> 3, aSeg = idx & 7;
        aSrc[q] = g_Lh + lbfOff + (size_t)(lrowBase + aRow) * N + aSeg * 8;
        aDst[q] = 2u * (AH_OFF + aRow * SA + aSeg * 8);
    }
    const uint16_t* bSrc[2]; uint32_t bDst[2];
    #pragma unroll
    for (int q = 0; q < 2; q++) {
        int idx = q * 256 + tid;
        int bRow = idx >> 3, bSeg = idx & 7;
        bSrc[q] = g_zh + (size_t)bRow * NT + zOff + bSeg * 8;
        bDst[q] = 2u * (BH_OFF + bRow * SA + bSeg * 8);
    }

    float acc[2][2][4];
    #pragma unroll
    for (int mt = 0; mt < 2; mt++)
        #pragma unroll
        for (int nt = 0; nt < 2; nt++)
            #pragma unroll
            for (int i = 0; i < 4; i++) acc[mt][nt][i] = 0.f;

    int sIssue = 0, sComp = 0;

    // ---- prologue: issue chunks 0,1,2 ----
    #pragma unroll
    for (int p = 0; p < 3; p++) {
        uint32_t st = smBase + (uint32_t)sIssue * STAGE_BYTES;
        int k0 = p * 64;
        #pragma unroll
        for (int q = 0; q < 2; q++) cp16(st + aDst[q], aSrc[q] + k0);
        #pragma unroll
        for (int q = 0; q < 2; q++) cp16(st + bDst[q], bSrc[q] + k0);
        CP_COMMIT();
        if (++sIssue == NSTAGE) sIssue = 0;
    }

    // ---- mainloop ----
    for (int cI = 0; cI < nc; cI++) {
        CP_WAIT2();
        __syncthreads();

        // issue chunk cI+3 (stage freed by chunk cI-1's compute last iteration)
        if (cI + 3 < nc) {
            uint32_t st = smBase + (uint32_t)sIssue * STAGE_BYTES;
            int k0 = (cI + 3) * 64;
            #pragma unroll
            for (int q = 0; q < 2; q++) cp16(st + aDst[q], aSrc[q] + k0);
            #pragma unroll
            for (int q = 0; q < 2; q++) cp16(st + bDst[q], bSrc[q] + k0);
        }
        CP_COMMIT();   // unconditional: keeps wait_group accounting correct at tail
        if (++sIssue == NSTAGE) sIssue = 0;

        // compute current chunk
        uint32_t stage = smBase + (uint32_t)sComp * STAGE_BYTES;
        if (++sComp == NSTAGE) sComp = 0;
        #pragma unroll
        for (int ks = 0; ks < 4; ks++) {
            uint32_t ah[2][4];
            #pragma unroll
            for (int mt = 0; mt < 2; mt++)
                ldsm_x4(ah[mt][0], ah[mt][1], ah[mt][2], ah[mt][3],
                        stage + aBase[mt] + ks * 32);
            uint32_t bv[2][2];
            ldsm_x4(bv[0][0], bv[0][1], bv[1][0], bv[1][1], stage + bBase + ks * 32);
            #pragma unroll
            for (int mt = 0; mt < 2; mt++)
                #pragma unroll
                for (int nt = 0; nt < 2; nt++)
                    mma_f16(acc[mt][nt], ah[mt], bv[nt]);
        }
    }

    // ---- epilogue: dinv row-scale + relu, write fp32 ----
    #pragma unroll
    for (int mt = 0; mt < 2; mt++) {
        int row0 = wm * 32 + mt * 16 + g;
        float dv0 = g_dinv[growBase + row0];
        float dv1 = g_dinv[growBase + row0 + 8];
        #pragma unroll
        for (int nt = 0; nt < 2; nt++) {
            int col = wn * 16 + nt * 8 + tg * 2;
            float* c = acc[mt][nt];
            float2 o0, o1;
            o0.x = fmaxf(c[0] * dv0, 0.f);
            o0.y = fmaxf(c[1] * dv0, 0.f);
            o1.x = fmaxf(c[2] * dv1, 0.f);
            o1.y = fmaxf(c[3] * dv1, 0.f);
            *(float2*)&dst[(size_t)(growBase + row0) * C + col]     = o0;
            *(float2*)&dst[(size_t)(growBase + row0 + 8) * C + col] = o1;
        }
    }
}

// ============================================================
// readout
// ============================================================
__global__ void zero_pooled_kernel() {
    int i = blockIdx.x * blockDim.x + threadIdx.x;
    if (i < 3 * NB * C) g_pooled[i] = 0.f;
}

__global__ void pool_kernel(const int* __restrict__ bel0,
                            const int* __restrict__ bel1,
                            const int* __restrict__ bel2) {
    int grow = blockIdx.x;
    int rank, lr;
    if (grow < NR0)            { rank = 0; lr = grow; }
    else if (grow < NR0 + NR1) { rank = 1; lr = grow - NR0; }
    else                       { rank = 2; lr = grow - NR0 - NR1; }
    const int* bel = (rank == 0) ? bel0 : (rank == 1 ? bel1 : bel2);
    int b = bel[lr];
    float v = g_xB[(size_t)grow * C + threadIdx.x];
    atomicAdd(&g_pooled[rank * NB * C + b * C + threadIdx.x], v);
}

__global__ void out_kernel(const float* __restrict__ Wr0, const float* __restrict__ br0,
                           const float* __restrict__ Wr1, const float* __restrict__ br1,
                           const float* __restrict__ Wr2, const float* __restrict__ br2,
                           float* __restrict__ out) {
    int b = blockIdx.x;
    int o = threadIdx.x;
    float acc = br0[o] + br1[o] + br2[o];
    const float* Wrs[3] = {Wr0, Wr1, Wr2};
    #pragma unroll
    for (int r = 0; r < 3; r++) {
        const float* Wr = Wrs[r];
        const float* p  = &g_pooled[r * NB * C + b * C];
        #pragma unroll 8
        for (int c = 0; c < C; c++) acc += p[c] * Wr[c * OUTC + o];
    }
    out[b * OUTC + o] = acc;
}

// ============================================================
extern "C" void kernel_launch(void* const* d_in, const int* in_sizes, int n_in,
                              void* d_out, int out_size) {
    const float* x0  = (const float*)d_in[0];
    const float* x1  = (const float*)d_in[1];
    const float* x2  = (const float*)d_in[2];
    const float* L0  = (const float*)d_in[3];
    const float* L1  = (const float*)d_in[4];
    const float* L2  = (const float*)d_in[5];
    const int*   bel0 = (const int*)d_in[6];
    const int*   bel1 = (const int*)d_in[7];
    const int*   bel2 = (const int*)d_in[8];
    const float* W0  = (const float*)d_in[9];
    const float* W1  = (const float*)d_in[10];
    const float* W2  = (const float*)d_in[11];
    const float* Wr0 = (const float*)d_in[12];
    const float* br0 = (const float*)d_in[13];
    const float* Wr1 = (const float*)d_in[14];
    const float* br1 = (const float*)d_in[15];
    const float* Wr2 = (const float*)d_in[16];
    const float* br2 = (const float*)d_in[17];

    cudaFuncSetAttribute(gemm_mma, cudaFuncAttributeMaxDynamicSharedMemorySize, GEMM_SMEM);

    dinv_conv_kernel<<<NT, 128>>>(L0, L1, L2);

    for (int layer = 0; layer < 2; layer++) {
        xw_kernel<<<NT / 64, 256>>>(x0, x1, x2, W0, W1, W2, layer);
        gemm_mma<<<256, 256, GEMM_SMEM>>>(layer);
    }

    zero_pooled_kernel<<<(3 * NB * C + 255) / 256, 256>>>();
    pool_kernel<<<NT, 64>>>(bel0, bel1, bel2);
    out_kernel<<<NB, OUTC>>>(Wr0, br0, Wr1, br1, Wr2, br2, (float*)d_out);
}

// round 12
// speedup vs baseline: 2.1712x; 1.0333x over previous
#include <cuda_runtime.h>
#include <cuda_fp16.h>
#include <cstdint>

#define NR0 4096
#define NR1 8192
#define NR2 4096
#define NT  16384     // NR0+NR1+NR2
#define C   64
#define OUTC 32
#define NB  64

// fp16 copies of the L matrices (written once by dinv_conv_kernel)
#define LBF_OFF0 0
#define LBF_OFF1 ((size_t)NR0 * NR0)
#define LBF_OFF2 (LBF_OFF1 + (size_t)NR1 * NR1)
#define LBF_TOTAL (LBF_OFF2 + (size_t)NR2 * NR2)

// ---- scratch (device globals; no allocation allowed) ----
__device__ float    g_dinv[NT];
__device__ uint16_t g_Lh[LBF_TOTAL];    // fp16 L
__device__ uint16_t g_zh[C * NT];       // fp16 z^T [C][NT] (K-major B operand)
__device__ float    g_xA[NT * C];       // layer outputs (pre-relu; consumers apply relu)
__device__ float    g_xB[NT * C];
__device__ float    g_pooled[3 * NB * C];

// ============================================================
// helpers
// ============================================================
__device__ __forceinline__ uint32_t pack_f16(float lo, float hi) {
    __half2 h = __floats2half2_rn(lo, hi);   // lo -> low 16 bits
    return *(uint32_t*)&h;
}
__device__ __forceinline__ void mma_f16(float* c, const uint32_t* a, const uint32_t* b) {
    asm volatile("mma.sync.aligned.m16n8k16.row.col.f32.f16.f16.f32 "
        "{%0,%1,%2,%3}, {%4,%5,%6,%7}, {%8,%9}, {%0,%1,%2,%3};"
        : "+f"(c[0]), "+f"(c[1]), "+f"(c[2]), "+f"(c[3])
        : "r"(a[0]), "r"(a[1]), "r"(a[2]), "r"(a[3]), "r"(b[0]), "r"(b[1]));
}
__device__ __forceinline__ void ldsm_x4(uint32_t& r0, uint32_t& r1, uint32_t& r2,
                                        uint32_t& r3, uint32_t addr) {
    asm volatile("ldmatrix.sync.aligned.m8n8.x4.shared.b16 {%0,%1,%2,%3}, [%4];"
                 : "=r"(r0), "=r"(r1), "=r"(r2), "=r"(r3) : "r"(addr));
}
__device__ __forceinline__ void cp16(uint32_t smaddr, const void* g) {
    asm volatile("cp.async.cg.shared.global [%0], [%1], 16;" :: "r"(smaddr), "l"(g));
}
#define CP_COMMIT() asm volatile("cp.async.commit_group;" ::: "memory")
#define CP_WAIT2()  asm volatile("cp.async.wait_group 2;" ::: "memory")

// ============================================================
// fused: dinv[i] = rsqrt(rowsum |L_i|)  AND  g_Lh = fp16(L)
// ============================================================
__global__ void dinv_conv_kernel(const float* __restrict__ L0,
                                 const float* __restrict__ L1,
                                 const float* __restrict__ L2) {
    int grow = blockIdx.x;
    const float* L; int N; int lr; size_t lbfOff;
    if (grow < NR0)             { L = L0; N = NR0; lr = grow;             lbfOff = LBF_OFF0; }
    else if (grow < NR0 + NR1)  { L = L1; N = NR1; lr = grow - NR0;       lbfOff = LBF_OFF1; }
    else                        { L = L2; N = NR2; lr = grow - NR0 - NR1; lbfOff = LBF_OFF2; }

    const float4* row = (const float4*)(L + (size_t)lr * N);
    uint2* rowOut = (uint2*)(g_Lh + lbfOff + (size_t)lr * N);
    int n4 = N >> 2;
    float s = 0.f;
    for (int j = threadIdx.x; j < n4; j += blockDim.x) {
        float4 v = row[j];
        s += fabsf(v.x) + fabsf(v.y) + fabsf(v.z) + fabsf(v.w);
        rowOut[j] = make_uint2(pack_f16(v.x, v.y), pack_f16(v.z, v.w));
    }
    __shared__ float red[4];
    for (int o = 16; o > 0; o >>= 1) s += __shfl_down_sync(0xffffffffu, s, o);
    if ((threadIdx.x & 31) == 0) red[threadIdx.x >> 5] = s;
    __syncthreads();
    if (threadIdx.x == 0) {
        float d = red[0] + red[1] + red[2] + red[3];
        g_dinv[grow] = (d != 0.f) ? rsqrtf(d) : 0.f;
    }
}

// ============================================================
// zero the two layer-output accumulators (atomicAdd targets)
// ============================================================
__global__ void zero_x_kernel() {
    int i = blockIdx.x * blockDim.x + threadIdx.x;
    float4 z = make_float4(0.f, 0.f, 0.f, 0.f);
    ((float4*)g_xA)[i] = z;
    ((float4*)g_xB)[i] = z;
}

// ============================================================
// z = dinv .* (relu?(x) @ W[layer]); emit fp16 transposed [C][NT]
// 32 rows/block, 128 thr (16x8 grid, 4x4 reg tile). relu applied on
// load for layer 1 (gemm epilogue is linear / no relu).
// ============================================================
#define XSP 68   // xs row pitch in floats
#define ZSP 72   // zs row pitch in halves

__global__ __launch_bounds__(128) void xw_kernel(
    const float* __restrict__ x0, const float* __restrict__ x1,
    const float* __restrict__ x2,
    const float* __restrict__ W0, const float* __restrict__ W1,
    const float* __restrict__ W2, int layer)
{
    __shared__ __align__(16) char sbuf[16384 + 32 * XSP * 4];   // 25088 B
    float* Ws = (float*)sbuf;                   // [64][64]
    float* xs = (float*)(sbuf + 16384);         // [32][XSP]

    int growBase = blockIdx.x * 32;
    const float* W; const float* xsrc;
    if (growBase < NR0) {
        W = W0;
        xsrc = layer ? (g_xA + (size_t)growBase * C) : (x0 + (size_t)growBase * C);
    } else if (growBase < NR0 + NR1) {
        W = W1;
        xsrc = layer ? (g_xA + (size_t)growBase * C) : (x1 + (size_t)(growBase - NR0) * C);
    } else {
        W = W2;
        xsrc = layer ? (g_xA + (size_t)growBase * C) : (x2 + (size_t)(growBase - NR0 - NR1) * C);
    }
    W += layer * C * C;

    int tid = threadIdx.x;
    for (int i = tid; i < C * C; i += 128) Ws[i] = W[i];
    // xs: 32 rows x 16 float4 = 512 float4, 4 per thread; relu for layer 1
    for (int i = tid; i < 32 * 16; i += 128) {
        int row = i >> 4, q = i & 15;
        float4 v = *(const float4*)(xsrc + row * C + q * 4);
        if (layer) {
            v.x = fmaxf(v.x, 0.f); v.y = fmaxf(v.y, 0.f);
            v.z = fmaxf(v.z, 0.f); v.w = fmaxf(v.w, 0.f);
        }
        *(float4*)&xs[row * XSP + q * 4] = v;
    }
    __syncthreads();

    int tx = tid & 15, ty = tid >> 4;           // 16x8 thread grid; 4x4 tile each
    const float4* Ws4 = (const float4*)Ws;

    float acc[4][4];
    #pragma unroll
    for (int i = 0; i < 4; i++)
        #pragma unroll
        for (int j = 0; j < 4; j++) acc[i][j] = 0.f;

    #pragma unroll 8
    for (int k = 0; k < C; k++) {
        float4 w = Ws4[k * 16 + tx];
        #pragma unroll
        for (int i = 0; i < 4; i++) {
            float a = xs[(ty * 4 + i) * XSP + k];
            acc[i][0] += a * w.x;
            acc[i][1] += a * w.y;
            acc[i][2] += a * w.z;
            acc[i][3] += a * w.w;
        }
    }
    __syncthreads();   // xs/Ws reads done; sbuf may be overwritten

    // scale by dinv, convert fp16, stage into overlaid zs
    uint16_t* zs = (uint16_t*)sbuf;             // [32][ZSP] halves
    #pragma unroll
    for (int i = 0; i < 4; i++) {
        int row = ty * 4 + i;
        float dv = g_dinv[growBase + row];
        uint2 p;
        p.x = pack_f16(acc[i][0] * dv, acc[i][1] * dv);
        p.y = pack_f16(acc[i][2] * dv, acc[i][3] * dv);
        *(uint2*)&zs[row * ZSP + tx * 4] = p;
    }
    __syncthreads();

    // transposed write: thread -> channel c2, 16 consecutive rows (2 x uint4)
    int c2 = tid >> 1, seg = tid & 1;
    size_t base = (size_t)c2 * NT + growBase + seg * 16;
    uint16_t hv[16];
    #pragma unroll
    for (int j = 0; j < 16; j++) hv[j] = zs[(seg * 16 + j) * ZSP + c2];
    *(uint4*)&g_zh[base]     = *(uint4*)hv;
    *(uint4*)&g_zh[base + 8] = *(uint4*)(hv + 8);
}

// ============================================================
// cp.async fp16 GEMM, uniform split-K tiles:
//   dst += dinv .* (L[:, kslice] @ z[kslice])   (atomicAdd; no relu)
// BM=64, BN=64, BK=64, K-slice = 2048 (nc = 32 chunks for every CTA).
// Tiles: rank1 128 mtiles x splitK4 = 512; rank0/2 64 x splitK2 = 128 each.
// 768 uniform CTAs -> hardware work-stealing kills the tail.
// ============================================================
#define SA 72   // smem row pitch in halves (64 data + 8 pad); 144B
#define AH_OFF 0
#define BH_OFF (64 * SA)
#define STAGE_HALVES (2 * 64 * SA)           // 9216 halves = 18432 B
#define STAGE_BYTES  (STAGE_HALVES * 2)
#define NSTAGE 4
#define GEMM_SMEM (NSTAGE * STAGE_BYTES)     // 73728 B
#define KSLICE 2048
#define NCHUNK (KSLICE / 64)                 // 32

__global__ __launch_bounds__(256, 2) void gemm_mma(int layer)
{
    extern __shared__ __align__(16) uint16_t sm[];

    int bx = blockIdx.x;
    int N, lrowBase, growBase, kBase; size_t lbfOff;
    if (bx < 512) {
        N = NR1; int mt = bx >> 2; lrowBase = mt * 64; growBase = NR0 + lrowBase;
        kBase = (bx & 3) * KSLICE; lbfOff = LBF_OFF1;
    } else if (bx < 640) {
        int t = bx - 512;
        N = NR0; lrowBase = (t >> 1) * 64; growBase = lrowBase;
        kBase = (t & 1) * KSLICE; lbfOff = LBF_OFF0;
    } else {
        int t = bx - 640;
        N = NR2; lrowBase = (t >> 1) * 64; growBase = NR0 + NR1 + lrowBase;
        kBase = (t & 1) * KSLICE; lbfOff = LBF_OFF2;
    }
    int zOff = growBase - lrowBase;
    float* dst = layer ? g_xB : g_xA;

    int tid = threadIdx.x;
    int wid = tid >> 5, lane = tid & 31;
    int g = lane >> 2, tg = lane & 3;
    int wm = wid >> 2, wn = wid & 3;     // 2m x 4n warp grid, tile m32n16

    uint32_t smBase = (uint32_t)__cvta_generic_to_shared(sm);

    // ---- ldmatrix lane byte offsets (within stage; +ks*32 bytes per k16 step) ----
    uint32_t aBase[2];
    #pragma unroll
    for (int mt = 0; mt < 2; mt++) {
        int row = wm * 32 + mt * 16 + (lane & 15);
        int col = (lane & 16) ? 8 : 0;
        aBase[mt] = 2u * (AH_OFF + row * SA + col);
    }
    uint32_t bBase;
    {
        int row = wn * 16 + (lane & 7) + ((lane & 16) >> 1);
        int col = (lane & 8) ? 8 : 0;
        bBase = 2u * (BH_OFF + row * SA + col);
    }

    // ---- cp.async loader setup (per chunk: A 8KB + B 8KB; 4 x 16B/thread) ----
    const uint16_t* aSrc[2]; uint32_t aDst[2];
    #pragma unroll
    for (int q = 0; q < 2; q++) {
        int idx = q * 256 + tid;
        int aRow = idx >> 3, aSeg = idx & 7;
        aSrc[q] = g_Lh + lbfOff + (size_t)(lrowBase + aRow) * N + kBase + aSeg * 8;
        aDst[q] = 2u * (AH_OFF + aRow * SA + aSeg * 8);
    }
    const uint16_t* bSrc[2]; uint32_t bDst[2];
    #pragma unroll
    for (int q = 0; q < 2; q++) {
        int idx = q * 256 + tid;
        int bRow = idx >> 3, bSeg = idx & 7;
        bSrc[q] = g_zh + (size_t)bRow * NT + zOff + kBase + bSeg * 8;
        bDst[q] = 2u * (BH_OFF + bRow * SA + bSeg * 8);
    }

    float acc[2][2][4];
    #pragma unroll
    for (int mt = 0; mt < 2; mt++)
        #pragma unroll
        for (int nt = 0; nt < 2; nt++)
            #pragma unroll
            for (int i = 0; i < 4; i++) acc[mt][nt][i] = 0.f;

    int sIssue = 0, sComp = 0;

    // ---- prologue: issue chunks 0,1,2 ----
    #pragma unroll
    for (int p = 0; p < 3; p++) {
        uint32_t st = smBase + (uint32_t)sIssue * STAGE_BYTES;
        int k0 = p * 64;
        #pragma unroll
        for (int q = 0; q < 2; q++) cp16(st + aDst[q], aSrc[q] + k0);
        #pragma unroll
        for (int q = 0; q < 2; q++) cp16(st + bDst[q], bSrc[q] + k0);
        CP_COMMIT();
        if (++sIssue == NSTAGE) sIssue = 0;
    }

    // ---- mainloop ----
    for (int cI = 0; cI < NCHUNK; cI++) {
        CP_WAIT2();
        __syncthreads();

        if (cI + 3 < NCHUNK) {
            uint32_t st = smBase + (uint32_t)sIssue * STAGE_BYTES;
            int k0 = (cI + 3) * 64;
            #pragma unroll
            for (int q = 0; q < 2; q++) cp16(st + aDst[q], aSrc[q] + k0);
            #pragma unroll
            for (int q = 0; q < 2; q++) cp16(st + bDst[q], bSrc[q] + k0);
        }
        CP_COMMIT();   // unconditional: keeps wait_group accounting correct at tail
        if (++sIssue == NSTAGE) sIssue = 0;

        uint32_t stage = smBase + (uint32_t)sComp * STAGE_BYTES;
        if (++sComp == NSTAGE) sComp = 0;
        #pragma unroll
        for (int ks = 0; ks < 4; ks++) {
            uint32_t ah[2][4];
            #pragma unroll
            for (int mt = 0; mt < 2; mt++)
                ldsm_x4(ah[mt][0], ah[mt][1], ah[mt][2], ah[mt][3],
                        stage + aBase[mt] + ks * 32);
            uint32_t bv[2][2];
            ldsm_x4(bv[0][0], bv[0][1], bv[1][0], bv[1][1], stage + bBase + ks * 32);
            #pragma unroll
            for (int mt = 0; mt < 2; mt++)
                #pragma unroll
                for (int nt = 0; nt < 2; nt++)
                    mma_f16(acc[mt][nt], ah[mt], bv[nt]);
        }
    }

    // ---- epilogue: dinv row-scale, atomicAdd partial (no relu) ----
    #pragma unroll
    for (int mt = 0; mt < 2; mt++) {
        int row0 = wm * 32 + mt * 16 + g;
        float dv0 = g_dinv[growBase + row0];
        float dv1 = g_dinv[growBase + row0 + 8];
        #pragma unroll
        for (int nt = 0; nt < 2; nt++) {
            int col = wn * 16 + nt * 8 + tg * 2;
            float* c = acc[mt][nt];
            float* p0 = &dst[(size_t)(growBase + row0) * C + col];
            float* p1 = &dst[(size_t)(growBase + row0 + 8) * C + col];
            atomicAdd(p0,     c[0] * dv0);
            atomicAdd(p0 + 1, c[1] * dv0);
            atomicAdd(p1,     c[2] * dv1);
            atomicAdd(p1 + 1, c[3] * dv1);
        }
    }
}

// ============================================================
// readout (relu applied on read of final layer output)
// ============================================================
__global__ void zero_pooled_kernel() {
    int i = blockIdx.x * blockDim.x + threadIdx.x;
    if (i < 3 * NB * C) g_pooled[i] = 0.f;
}

__global__ void pool_kernel(const int* __restrict__ bel0,
                            const int* __restrict__ bel1,
                            const int* __restrict__ bel2) {
    int grow = blockIdx.x;
    int rank, lr;
    if (grow < NR0)            { rank = 0; lr = grow; }
    else if (grow < NR0 + NR1) { rank = 1; lr = grow - NR0; }
    else                       { rank = 2; lr = grow - NR0 - NR1; }
    const int* bel = (rank == 0) ? bel0 : (rank == 1 ? bel1 : bel2);
    int b = bel[lr];
    float v = fmaxf(g_xB[(size_t)grow * C + threadIdx.x], 0.f);
    atomicAdd(&g_pooled[rank * NB * C + b * C + threadIdx.x], v);
}

__global__ void out_kernel(const float* __restrict__ Wr0, const float* __restrict__ br0,
                           const float* __restrict__ Wr1, const float* __restrict__ br1,
                           const float* __restrict__ Wr2, const float* __restrict__ br2,
                           float* __restrict__ out) {
    int b = blockIdx.x;
    int o = threadIdx.x;
    float acc = br0[o] + br1[o] + br2[o];
    const float* Wrs[3] = {Wr0, Wr1, Wr2};
    #pragma unroll
    for (int r = 0; r < 3; r++) {
        const float* Wr = Wrs[r];
        const float* p  = &g_pooled[r * NB * C + b * C];
        #pragma unroll 8
        for (int c = 0; c < C; c++) acc += p[c] * Wr[c * OUTC + o];
    }
    out[b * OUTC + o] = acc;
}

// ============================================================
extern "C" void kernel_launch(void* const* d_in, const int* in_sizes, int n_in,
                              void* d_out, int out_size) {
    const float* x0  = (const float*)d_in[0];
    const float* x1  = (const float*)d_in[1];
    const float* x2  = (const float*)d_in[2];
    const float* L0  = (const float*)d_in[3];
    const float* L1  = (const float*)d_in[4];
    const float* L2  = (const float*)d_in[5];
    const int*   bel0 = (const int*)d_in[6];
    const int*   bel1 = (const int*)d_in[7];
    const int*   bel2 = (const int*)d_in[8];
    const float* W0  = (const float*)d_in[9];
    const float* W1  = (const float*)d_in[10];
    const float* W2  = (const float*)d_in[11];
    const float* Wr0 = (const float*)d_in[12];
    const float* br0 = (const float*)d_in[13];
    const float* Wr1 = (const float*)d_in[14];
    const float* br1 = (const float*)d_in[15];
    const float* Wr2 = (const float*)d_in[16];
    const float* br2 = (const float*)d_in[17];

    cudaFuncSetAttribute(gemm_mma, cudaFuncAttributeMaxDynamicSharedMemorySize, GEMM_SMEM);

    dinv_conv_kernel<<<NT, 128>>>(L0, L1, L2);
    zero_x_kernel<<<(NT * C / 4) / 256, 256>>>();   // zero g_xA + g_xB

    for (int layer = 0; layer < 2; layer++) {
        xw_kernel<<<NT / 32, 128>>>(x0, x1, x2, W0, W1, W2, layer);
        gemm_mma<<<768, 256, GEMM_SMEM>>>(layer);
    }

    zero_pooled_kernel<<<(3 * NB * C + 255) / 256, 256>>>();
    pool_kernel<<<NT, 64>>>(bel0, bel1, bel2);
    out_kernel<<<NB, OUTC>>>(Wr0, br0, Wr1, br1, Wr2, br2, (float*)d_out);
}